// round 8
// baseline (speedup 1.0000x reference)
#include <cuda_runtime.h>
#include <cuda_fp16.h>
#include <math.h>
#include <stdint.h>

// ---------------------------------------------------------------------------
// Scratch (device globals; allocation-free). ~110 MB total.
// ---------------------------------------------------------------------------
__device__ __align__(16) __half g_Whi[2097152];   // [O][Kpad] hi, max 128x16384
__device__ __align__(16) __half g_Wlo[2097152];   // [O][Kpad] lo
__device__ __align__(16) __half g_exp[33554432];  // expanded activations, 16B/elem
__device__ __align__(16) __half g_expZero[8];     // e(0) for pads
__device__ float g_act1[4194304];     // (512,16,16,32) NHWC
__device__ float g_act2[2097152];     // (512,8,8,64)   NHWC
__device__ float g_act3[1048576];     // (512,4,4,128)  NHWC
__device__ float g_act4[262144];      // (512,2,2,128)  NHWC
__device__ float g_part[4194304];     // split-K partials
__device__ float g_bnS1[64],  g_bnT1[64];
__device__ float g_bnS2[128], g_bnT2[128];
__device__ float g_bnS3[128], g_bnT3[128];

// ---------------------------------------------------------------------------
// Helpers
// ---------------------------------------------------------------------------
__device__ __forceinline__ uint32_t smem_u32(const void* p) {
    uint32_t a;
    asm("{ .reg .u64 t; cvta.to.shared.u64 t, %1; cvt.u32.u64 %0, t; }"
        : "=r"(a) : "l"(p));
    return a;
}
__device__ __forceinline__ uint32_t sw128(uint32_t off) {
    return off ^ ((off >> 3) & 0x70);
}
__device__ __forceinline__ void cp16(uint32_t dst, const void* src) {
    asm volatile("cp.async.cg.shared.global [%0], [%1], 16;"
                 :: "r"(dst), "l"(src) : "memory");
}
__device__ __forceinline__ void cp_commit() {
    asm volatile("cp.async.commit_group;" ::: "memory");
}
template <int N>
__device__ __forceinline__ void cp_wait() {
    asm volatile("cp.async.wait_group %0;" :: "n"(N) : "memory");
}
__device__ __forceinline__ void ldsm_x4(uint32_t* r, uint32_t addr) {
    asm volatile("ldmatrix.sync.aligned.m8n8.x4.shared.b16 {%0,%1,%2,%3}, [%4];"
                 : "=r"(r[0]), "=r"(r[1]), "=r"(r[2]), "=r"(r[3]) : "r"(addr));
}
__device__ __forceinline__ void mma16816(float* c, const uint32_t* a, const uint32_t* b) {
    asm volatile(
        "mma.sync.aligned.m16n8k16.row.col.f32.f16.f16.f32 "
        "{%0,%1,%2,%3}, {%4,%5,%6,%7}, {%8,%9}, {%0,%1,%2,%3};"
        : "+f"(c[0]), "+f"(c[1]), "+f"(c[2]), "+f"(c[3])
        : "r"(a[0]), "r"(a[1]), "r"(a[2]), "r"(a[3]), "r"(b[0]), "r"(b[1]));
}
__device__ __forceinline__ uint32_t h2pack(float a, float b) {
    __half2 h = __floats2half2_rn(a, b);
    return *reinterpret_cast<uint32_t*>(&h);
}

// ---------------------------------------------------------------------------
// Quadratic B-spline bases (grid_size=3, order=2) -> 5 bases; mirrors reference.
// ---------------------------------------------------------------------------
__device__ __forceinline__ void spline5(float x, float* bo) {
    float g[8];
#pragma unroll
    for (int i = 0; i < 8; i++) g[i] = (float)(i - 2) * (2.0f / 3.0f) - 1.0f;
    float b0[7];
#pragma unroll
    for (int j = 0; j < 7; j++) b0[j] = (x >= g[j] && x < g[j + 1]) ? 1.0f : 0.0f;
    float b1[6];
#pragma unroll
    for (int j = 0; j < 6; j++)
        b1[j] = (x - g[j]) * (1.0f / (g[j + 1] - g[j])) * b0[j]
              + (g[j + 2] - x) * (1.0f / (g[j + 2] - g[j + 1])) * b0[j + 1];
#pragma unroll
    for (int j = 0; j < 5; j++)
        bo[j] = (x - g[j]) * (1.0f / (g[j + 2] - g[j])) * b1[j]
              + (g[j + 3] - x) * (1.0f / (g[j + 3] - g[j + 1])) * b1[j + 1];
}

// ---------------------------------------------------------------------------
// Expansion: per source element -> 8 fp16 [relu, 5 bases, 0, 0] (16 B).
// Optional preceding-BN affine (channel = idx % C for NHWC activations).
// ---------------------------------------------------------------------------
__global__ void expand_kernel(const float* __restrict__ src,
                              __half* __restrict__ dst,
                              const float* __restrict__ bns,
                              const float* __restrict__ bnt, int N, int C) {
    int i = blockIdx.x * blockDim.x + threadIdx.x;
    if (i >= N) return;
    float v = src[i];
    if (bns) v = fmaf(v, bns[i % C], bnt[i % C]);
    float vals[6];
    vals[0] = fmaxf(v, 0.0f);
    spline5(v, &vals[1]);
    uint4 o;
    o.x = h2pack(vals[0], vals[1]);
    o.y = h2pack(vals[2], vals[3]);
    o.z = h2pack(vals[4], vals[5]);
    o.w = 0u;
    *(uint4*)&dst[(size_t)i * 8] = o;
}

__global__ void expand_zero_kernel(__half* __restrict__ dst) {
    float vals[6];
    vals[0] = 0.0f;
    spline5(0.0f, &vals[1]);
    uint4 o;
    o.x = h2pack(vals[0], vals[1]);
    o.y = h2pack(vals[2], vals[3]);
    o.z = h2pack(vals[4], vals[5]);
    o.w = 0u;
    *(uint4*)dst = o;
}

// ---------------------------------------------------------------------------
// Build split weights (fp16 hi/lo): W[o][k], k = f*8 + t.
// ---------------------------------------------------------------------------
__global__ void build_wsplit_kernel(const float* __restrict__ bw,
                                    const float* __restrict__ sw,
                                    const float* __restrict__ sc,
                                    __half* __restrict__ whi,
                                    __half* __restrict__ wlo,
                                    int F, int O, int Kpad) {
    int idx = blockIdx.x * blockDim.x + threadIdx.x;
    if (idx >= O * Kpad) return;
    int o = idx / Kpad;
    int k = idx % Kpad;
    int f = k >> 3;
    int t = k & 7;
    float val = 0.0f;
    if (t == 0)      val = bw[o * F + f];
    else if (t <= 5) val = sw[(o * F + f) * 5 + (t - 1)] * sc[o * F + f];
    __half h = __float2half_rn(val);
    __half l = __float2half_rn(val - __half2float(h));
    whi[idx] = h;
    wlo[idx] = l;
}

// ---------------------------------------------------------------------------
// Fused KAN-conv GEMM on mma.sync (fp16 A, fp16 W hi/lo 2-term, fp32 accum).
// A tile = cp.async gather of precomputed 16B expansions (pads -> expZero).
// Double-buffered cp.async pipeline. grid.z splits the feature range.
// ---------------------------------------------------------------------------
template <int BN>
__global__ __launch_bounds__(256)
void kan_mma_kernel(const __half* __restrict__ expv,
                    const __half* __restrict__ Whi,
                    const __half* __restrict__ Wlo,
                    const __half* __restrict__ expZero,
                    float* __restrict__ C,
                    int M, int O, int Cin, int Hin, int hs, int nchw,
                    int fCount, int Kpad) {
    constexpr int BM = 128;
    constexpr int BF = 8;                  // features per chunk -> 64 fp16 k
    constexpr int WN = BN / 2;
    constexpr int NA = WN / 8;
    constexpr int NPAIR = NA / 2;
    constexpr int A_BYTES = BM * 128;      // 16 KB
    constexpr int B_BYTES = BN * 128;      // 8 or 4 KB
    constexpr int BUF_STRIDE = A_BYTES + 2 * B_BYTES;
    constexpr int BITER = (BN * 8) / 256;

    extern __shared__ char dynsmem[];
    uintptr_t tbase = ((uintptr_t)dynsmem + 1023) & ~(uintptr_t)1023;
    const uint32_t base0 = smem_u32((void*)tbase);

    const int tid = threadIdx.x;
    const int lane = tid & 31;
    const int wid = tid >> 5;
    const int warp_m = wid & 3;
    const int warp_n = wid >> 2;

    const int z = blockIdx.z;
    const int fBase = z * fCount;
    const int row0 = blockIdx.x * BM;
    const int col0 = blockIdx.y * BN;
    float* Cz = C + z * M * O;

    float acc[2][NA][4];
#pragma unroll
    for (int i = 0; i < 2; i++)
#pragma unroll
        for (int j = 0; j < NA; j++)
#pragma unroll
            for (int q = 0; q < 4; q++) acc[i][j][q] = 0.0f;

    const int Hout = 1 << hs;
    const int hwMask = (Hout * Hout) - 1;
    const int hwShift = 2 * hs;
    const int NC = fCount / BF;

    const uint32_t aRowOff = (uint32_t)(lane & 15) * 128 + ((uint32_t)(lane >> 4) << 4);
    const uint32_t bRowOff = ((uint32_t)((lane & 7) + ((lane >> 4) << 3))) * 128 +
                             (((uint32_t)(lane >> 3) & 1u) << 4);

    auto issueChunk = [&](int cc) {
        const int buf = cc & 1;
        const uint32_t A0 = base0 + buf * BUF_STRIDE;
        const uint32_t BH0 = A0 + A_BYTES;
        const uint32_t BL0 = BH0 + B_BYTES;
        // A: 4 x 16B gathers per thread
#pragma unroll
        for (int it = 0; it < 4; it++) {
            const int l = tid + it * 256;
            const int mLocal = l & (BM - 1);
            const int fl = l >> 7;
            const int m = row0 + mLocal;
            const int f = fBase + cc * BF + fl;
            const int p = m & hwMask;
            const int b = m >> hwShift;
            const int ho = p >> hs, wo = p & (Hout - 1);
            const int c = f >> 4;
            const int r = f & 15;
            const int ih = 2 * ho + (r >> 2) - 1;
            const int iw = 2 * wo + (r & 3) - 1;
            const __half* gp = expZero;
            if ((unsigned)ih < (unsigned)Hin && (unsigned)iw < (unsigned)Hin) {
                int off = nchw
                    ? (((b * Cin + c) * Hin + ih) * Hin + iw)
                    : (((b * Hin + ih) * Hin + iw) * Cin + c);
                gp = expv + (size_t)off * 8;
            }
            cp16(A0 + sw128((uint32_t)(mLocal * 128 + fl * 16)), gp);
        }
        // B: prebuilt weights
        const int kG = (fBase + cc * BF) * 8;
#pragma unroll
        for (int it = 0; it < BITER; it++) {
            const int l = tid + it * 256;
            const int rown = l >> 3;
            const int cg = l & 7;
            const int gidx = (col0 + rown) * Kpad + kG + cg * 8;
            const uint32_t sw = sw128((uint32_t)(rown * 128 + cg * 16));
            cp16(BH0 + sw, Whi + gidx);
            cp16(BL0 + sw, Wlo + gidx);
        }
        cp_commit();
    };

    issueChunk(0);

    for (int cch = 0; cch < NC; cch++) {
        if (cch + 1 < NC) {
            issueChunk(cch + 1);
            cp_wait<1>();
        } else {
            cp_wait<0>();
        }
        __syncthreads();

        const int buf = cch & 1;
        const uint32_t A0 = base0 + buf * BUF_STRIDE;
        const uint32_t BH0 = A0 + A_BYTES;
        const uint32_t BL0 = BH0 + B_BYTES;

#pragma unroll
        for (int ks = 0; ks < 4; ks++) {
            const uint32_t kb = (uint32_t)(ks * 32);
            uint32_t ah[2][4];
#pragma unroll
            for (int am = 0; am < 2; am++) {
                const uint32_t off =
                    sw128((uint32_t)((warp_m * 32 + am * 16) * 128) + aRowOff + kb);
                ldsm_x4(ah[am], A0 + off);
            }
            uint32_t bh[NA][2], bl[NA][2];
#pragma unroll
            for (int pr = 0; pr < NPAIR; pr++) {
                const uint32_t off =
                    sw128((uint32_t)((warp_n * WN + pr * 16) * 128) + bRowOff + kb);
                uint32_t t[4];
                ldsm_x4(t, BH0 + off);
                bh[2 * pr][0] = t[0]; bh[2 * pr][1] = t[1];
                bh[2 * pr + 1][0] = t[2]; bh[2 * pr + 1][1] = t[3];
                ldsm_x4(t, BL0 + off);
                bl[2 * pr][0] = t[0]; bl[2 * pr][1] = t[1];
                bl[2 * pr + 1][0] = t[2]; bl[2 * pr + 1][1] = t[3];
            }
#pragma unroll
            for (int am = 0; am < 2; am++)
#pragma unroll
                for (int an = 0; an < NA; an++) {
                    mma16816(acc[am][an], ah[am], bh[an]);
                    mma16816(acc[am][an], ah[am], bl[an]);
                }
        }
        // ensure all warps finished reading buf before chunk cch+2 overwrites it
        __syncthreads();
    }

    // ---- epilogue: write fragments ----
#pragma unroll
    for (int am = 0; am < 2; am++) {
        const int rr = row0 + warp_m * 32 + am * 16 + (lane >> 2);
#pragma unroll
        for (int an = 0; an < NA; an++) {
            const int cc = col0 + warp_n * WN + an * 8 + (lane & 3) * 2;
            *(float2*)&Cz[rr * O + cc] = make_float2(acc[am][an][0], acc[am][an][1]);
            *(float2*)&Cz[(rr + 8) * O + cc] = make_float2(acc[am][an][2], acc[am][an][3]);
        }
    }
}

// ---------------------------------------------------------------------------
// Split-K reduce (deterministic)
// ---------------------------------------------------------------------------
__global__ void reduce_splitk_kernel(const float* __restrict__ part,
                                     float* __restrict__ out, int MN, int S) {
    int idx = blockIdx.x * blockDim.x + threadIdx.x;
    if (idx >= MN) return;
    float a = 0.0f;
    for (int s = 0; s < S; s++) a += part[s * MN + idx];
    out[idx] = a;
}

// ---------------------------------------------------------------------------
// BN statistics -> fused affine y = x*s + t (double accum, deterministic).
// ---------------------------------------------------------------------------
__global__ void bnstats_kernel(const float* __restrict__ act,
                               const float* __restrict__ gamma,
                               const float* __restrict__ beta,
                               float* __restrict__ s_out,
                               float* __restrict__ t_out, int n, int C) {
    int c = blockIdx.x;
    double sum = 0.0, sum2 = 0.0;
    for (int e = threadIdx.x; e < n; e += blockDim.x) {
        float v = act[e * C + c];
        sum += v;
        sum2 += (double)v * v;
    }
    __shared__ double shs[256];
    __shared__ double sh2[256];
    shs[threadIdx.x] = sum;
    sh2[threadIdx.x] = sum2;
    __syncthreads();
    for (int o = 128; o > 0; o >>= 1) {
        if (threadIdx.x < o) {
            shs[threadIdx.x] += shs[threadIdx.x + o];
            sh2[threadIdx.x] += sh2[threadIdx.x + o];
        }
        __syncthreads();
    }
    if (threadIdx.x == 0) {
        double mean = shs[0] / n;
        double var = sh2[0] / n - mean * mean;
        double sv = (double)gamma[c] * rsqrt(var + 1e-5);
        s_out[c] = (float)sv;
        t_out[c] = (float)((double)beta[c] - mean * sv);
    }
}

// ---------------------------------------------------------------------------
// Head: BN3 affine + avgpool(2x2) + fc(128->1) + sigmoid.
// ---------------------------------------------------------------------------
__global__ void head_kernel(const float* __restrict__ act4,
                            const float* __restrict__ s,
                            const float* __restrict__ t,
                            const float* __restrict__ fcw,
                            const float* __restrict__ fcb,
                            float* __restrict__ out) {
    int b = blockIdx.x;
    int c = threadIdx.x;  // 128 threads
    const float* p = act4 + b * 4 * 128;
    float mval = 0.25f * (p[c] + p[128 + c] + p[256 + c] + p[384 + c]);
    float v = (s[c] * mval + t[c]) * fcw[c];
    __shared__ float sh[128];
    sh[c] = v;
    __syncthreads();
    for (int o = 64; o > 0; o >>= 1) {
        if (c < o) sh[c] += sh[c + o];
        __syncthreads();
    }
    if (c == 0) {
        float zv = sh[0] + fcb[0];
        out[b] = 1.0f / (1.0f + expf(-zv));
    }
}

// ---------------------------------------------------------------------------
// Launch
// ---------------------------------------------------------------------------
extern "C" void kernel_launch(void* const* d_in, const int* in_sizes, int n_in,
                              void* d_out, int out_size) {
    const float* x   = (const float*)d_in[0];
    const float* bw1 = (const float*)d_in[1];
    const float* sw1 = (const float*)d_in[2];
    const float* sc1 = (const float*)d_in[3];
    const float* bw2 = (const float*)d_in[4];
    const float* sw2 = (const float*)d_in[5];
    const float* sc2 = (const float*)d_in[6];
    const float* bw3 = (const float*)d_in[7];
    const float* sw3 = (const float*)d_in[8];
    const float* sc3 = (const float*)d_in[9];
    const float* bw4 = (const float*)d_in[10];
    const float* sw4 = (const float*)d_in[11];
    const float* sc4 = (const float*)d_in[12];
    const float* g1  = (const float*)d_in[13];
    const float* b1  = (const float*)d_in[14];
    const float* g2  = (const float*)d_in[15];
    const float* b2  = (const float*)d_in[16];
    const float* g3  = (const float*)d_in[17];
    const float* b3  = (const float*)d_in[18];
    const float* fcw = (const float*)d_in[19];
    const float* fcb = (const float*)d_in[20];
    float* out = (float*)d_out;

    __half *whi, *wlo, *expv, *expz;
    float *act1, *act2, *act3, *act4, *part;
    float *s1, *t1, *s2, *t2, *s3, *t3;
    cudaGetSymbolAddress((void**)&whi, g_Whi);
    cudaGetSymbolAddress((void**)&wlo, g_Wlo);
    cudaGetSymbolAddress((void**)&expv, g_exp);
    cudaGetSymbolAddress((void**)&expz, g_expZero);
    cudaGetSymbolAddress((void**)&act1, g_act1);
    cudaGetSymbolAddress((void**)&act2, g_act2);
    cudaGetSymbolAddress((void**)&act3, g_act3);
    cudaGetSymbolAddress((void**)&act4, g_act4);
    cudaGetSymbolAddress((void**)&part, g_part);
    cudaGetSymbolAddress((void**)&s1, g_bnS1);
    cudaGetSymbolAddress((void**)&t1, g_bnT1);
    cudaGetSymbolAddress((void**)&s2, g_bnS2);
    cudaGetSymbolAddress((void**)&t2, g_bnT2);
    cudaGetSymbolAddress((void**)&s3, g_bnS3);
    cudaGetSymbolAddress((void**)&t3, g_bnT3);

    const int SMEM64 = 2 * (16384 + 2 * 64 * 128) + 1024;  // 66560
    const int SMEM32 = 2 * (16384 + 2 * 32 * 128) + 1024;  // 50176
    cudaFuncSetAttribute(kan_mma_kernel<32>,
                         cudaFuncAttributeMaxDynamicSharedMemorySize, SMEM32);
    cudaFuncSetAttribute(kan_mma_kernel<64>,
                         cudaFuncAttributeMaxDynamicSharedMemorySize, SMEM64);

    expand_zero_kernel<<<1, 1>>>(expz);

    // ---- Layer 1: (512,3,32,32) NCHW -> (512,16,16,32) NHWC ----------------
    {
        const int F = 48, O = 32, M = 512 * 16 * 16, Kpad = 8 * F;
        const int N = 512 * 3 * 32 * 32;
        build_wsplit_kernel<<<(O * Kpad + 255) / 256, 256>>>(bw1, sw1, sc1, whi, wlo, F, O, Kpad);
        expand_kernel<<<(N + 255) / 256, 256>>>(x, expv, nullptr, nullptr, N, 1);
        kan_mma_kernel<32><<<dim3(M / 128, 1, 1), 256, SMEM32>>>(
            expv, whi, wlo, expz, act1, M, O, 3, 32, 4, 1, F, Kpad);
    }
    // ---- Layer 2: -> (512,8,8,64) via split2, BN1 stats ---------------------
    {
        const int F = 512, O = 64, M = 512 * 8 * 8, Kpad = 8 * F;
        const int SPLIT = 2;
        const int N = 512 * 16 * 16 * 32;
        build_wsplit_kernel<<<(O * Kpad + 255) / 256, 256>>>(bw2, sw2, sc2, whi, wlo, F, O, Kpad);
        expand_kernel<<<(N + 255) / 256, 256>>>(act1, expv, nullptr, nullptr, N, 32);
        kan_mma_kernel<64><<<dim3(M / 128, 1, SPLIT), 256, SMEM64>>>(
            expv, whi, wlo, expz, part, M, O, 32, 16, 3, 0, F / SPLIT, Kpad);
        reduce_splitk_kernel<<<(M * O + 255) / 256, 256>>>(part, act2, M * O, SPLIT);
        bnstats_kernel<<<64, 256>>>(act2, g1, b1, s1, t1, 512 * 64, 64);
    }
    // ---- Layer 3: BN1 in expansion -> (512,4,4,128) via split4, BN2 ---------
    {
        const int F = 1024, O = 128, M = 512 * 4 * 4, Kpad = 8 * F;
        const int SPLIT = 4;
        const int N = 512 * 8 * 8 * 64;
        build_wsplit_kernel<<<(O * Kpad + 255) / 256, 256>>>(bw3, sw3, sc3, whi, wlo, F, O, Kpad);
        expand_kernel<<<(N + 255) / 256, 256>>>(act2, expv, s1, t1, N, 64);
        kan_mma_kernel<64><<<dim3(M / 128, O / 64, SPLIT), 256, SMEM64>>>(
            expv, whi, wlo, expz, part, M, O, 64, 8, 2, 0, F / SPLIT, Kpad);
        reduce_splitk_kernel<<<(M * O + 255) / 256, 256>>>(part, act3, M * O, SPLIT);
        bnstats_kernel<<<128, 256>>>(act3, g2, b2, s2, t2, 512 * 16, 128);
    }
    // ---- Layer 4: BN2 in expansion -> (512,2,2,128) via split8, BN3 ---------
    {
        const int F = 2048, O = 128, M = 512 * 2 * 2, Kpad = 8 * F;
        const int SPLIT = 8;
        const int N = 512 * 4 * 4 * 128;
        build_wsplit_kernel<<<(O * Kpad + 255) / 256, 256>>>(bw4, sw4, sc4, whi, wlo, F, O, Kpad);
        expand_kernel<<<(N + 255) / 256, 256>>>(act3, expv, s2, t2, N, 128);
        kan_mma_kernel<64><<<dim3(M / 128, O / 64, SPLIT), 256, SMEM64>>>(
            expv, whi, wlo, expz, part, M, O, 128, 4, 1, 0, F / SPLIT, Kpad);
        reduce_splitk_kernel<<<(M * O + 255) / 256, 256>>>(part, act4, M * O, SPLIT);
        bnstats_kernel<<<128, 256>>>(act4, g3, b3, s3, t3, 512 * 4, 128);
    }
    // ---- Head --------------------------------------------------------------
    head_kernel<<<512, 128>>>(act4, s3, t3, fcw, fcb, out);
}

// round 9
// speedup vs baseline: 3.7037x; 3.7037x over previous
#include <cuda_runtime.h>
#include <cuda_fp16.h>
#include <math.h>
#include <stdint.h>

// ---------------------------------------------------------------------------
// Scratch (device globals; allocation-free). ~42 MB total.
// ---------------------------------------------------------------------------
__device__ __align__(16) __half g_Whi[2097152];  // [O][Kpad] hi, max 128x16384
__device__ __align__(16) __half g_Wlo[2097152];  // [O][Kpad] lo
__device__ float g_act1[4194304];     // (512,16,16,32) NHWC
__device__ float g_act2[2097152];     // (512,8,8,64)   NHWC
__device__ float g_act3[1048576];     // (512,4,4,128)  NHWC
__device__ float g_act4[262144];      // (512,2,2,128)  NHWC
__device__ float g_part[4194304];     // split-K partials
__device__ float g_bnS1[64],  g_bnT1[64];
__device__ float g_bnS2[128], g_bnT2[128];
__device__ float g_bnS3[128], g_bnT3[128];

// ---------------------------------------------------------------------------
// Helpers
// ---------------------------------------------------------------------------
__device__ __forceinline__ uint32_t smem_u32(const void* p) {
    uint32_t a;
    asm("{ .reg .u64 t; cvta.to.shared.u64 t, %1; cvt.u32.u64 %0, t; }"
        : "=r"(a) : "l"(p));
    return a;
}
__device__ __forceinline__ uint32_t sw128(uint32_t off) {
    return off ^ ((off >> 3) & 0x70);
}
__device__ __forceinline__ void sts128(uint32_t addr, uint32_t a, uint32_t b,
                                       uint32_t c, uint32_t d) {
    asm volatile("st.shared.v4.b32 [%0], {%1, %2, %3, %4};"
                 :: "r"(addr), "r"(a), "r"(b), "r"(c), "r"(d) : "memory");
}
__device__ __forceinline__ void cp16(uint32_t dst, const void* src) {
    asm volatile("cp.async.cg.shared.global [%0], [%1], 16;"
                 :: "r"(dst), "l"(src) : "memory");
}
__device__ __forceinline__ void cp_commit() {
    asm volatile("cp.async.commit_group;" ::: "memory");
}
template <int N>
__device__ __forceinline__ void cp_wait() {
    asm volatile("cp.async.wait_group %0;" :: "n"(N) : "memory");
}
__device__ __forceinline__ void ldsm_x4(uint32_t* r, uint32_t addr) {
    asm volatile("ldmatrix.sync.aligned.m8n8.x4.shared.b16 {%0,%1,%2,%3}, [%4];"
                 : "=r"(r[0]), "=r"(r[1]), "=r"(r[2]), "=r"(r[3]) : "r"(addr));
}
__device__ __forceinline__ void mma16816(float* c, const uint32_t* a, const uint32_t* b) {
    asm volatile(
        "mma.sync.aligned.m16n8k16.row.col.f32.f16.f16.f32 "
        "{%0,%1,%2,%3}, {%4,%5,%6,%7}, {%8,%9}, {%0,%1,%2,%3};"
        : "+f"(c[0]), "+f"(c[1]), "+f"(c[2]), "+f"(c[3])
        : "r"(a[0]), "r"(a[1]), "r"(a[2]), "r"(a[3]), "r"(b[0]), "r"(b[1]));
}
__device__ __forceinline__ uint32_t h2pack(float a, float b) {
    __half2 h = __floats2half2_rn(a, b);
    return *reinterpret_cast<uint32_t*>(&h);
}

// ---------------------------------------------------------------------------
// Closed-form quadratic B-spline (grid_size=3, order=2, uniform knots
// g[i] = (i-2)*2/3 - 1). Exactly 3 non-zero bases at j = i-2, i-1, i where
// i is the containing order-0 interval; values {(1-t)^2/2, 1/2+t-t^2, t^2/2}.
// Matches the reference Cox-de Boor result to fp32 rounding.
// ---------------------------------------------------------------------------
__device__ __forceinline__ void spline5(float x, float* bo) {
    float u = (x + 7.0f / 3.0f) * 1.5f;   // (x - g0)/h
    float fi = floorf(u);
    int i = (int)fi;
    float t = u - fi;
    float omt = 1.0f - t;
    float q0 = 0.5f * omt * omt;
    float q2 = 0.5f * t * t;
    float q1 = 1.0f - q0 - q2;
#pragma unroll
    for (int j = 0; j < 5; j++) {
        float v = 0.0f;
        v = (j == i - 2) ? q0 : v;
        v = (j == i - 1) ? q1 : v;
        v = (j == i)     ? q2 : v;
        bo[j] = v;
    }
}

// ---------------------------------------------------------------------------
// Build split weights (fp16 hi/lo): W[o][k], k = f*8 + t; t=0 base w,
// t=1..5 spline w * scaler, t=6,7 zero pad.
// ---------------------------------------------------------------------------
__global__ void build_wsplit_kernel(const float* __restrict__ bw,
                                    const float* __restrict__ sw,
                                    const float* __restrict__ sc,
                                    __half* __restrict__ whi,
                                    __half* __restrict__ wlo,
                                    int F, int O, int Kpad) {
    int idx = blockIdx.x * blockDim.x + threadIdx.x;
    if (idx >= O * Kpad) return;
    int o = idx / Kpad;
    int k = idx % Kpad;
    int f = k >> 3;
    int t = k & 7;
    float val = 0.0f;
    if (t == 0)      val = bw[o * F + f];
    else if (t <= 5) val = sw[(o * F + f) * 5 + (t - 1)] * sc[o * F + f];
    __half h = __float2half_rn(val);
    __half l = __float2half_rn(val - __half2float(h));
    whi[idx] = h;
    wlo[idx] = l;
}

// ---------------------------------------------------------------------------
// Fused KAN-conv GEMM on mma.sync (fp16 A single-term, fp16 W hi/lo 2-term,
// fp32 accum). BM=128 x BN, 8 warps (4M x 2N). Double-buffered chunks:
// A gathered+expanded in registers (spline closed-form) then STS; B via
// cp.async. One __syncthreads per chunk. grid.z splits the feature range.
// ---------------------------------------------------------------------------
template <int BN>
__global__ __launch_bounds__(256, 3)
void kan_mma_kernel(const float* __restrict__ src,
                    const __half* __restrict__ Whi,
                    const __half* __restrict__ Wlo,
                    float* __restrict__ C,
                    const float* __restrict__ bns,
                    const float* __restrict__ bnt,
                    int M, int O, int Cin, int Hin, int hs, int nchw,
                    int fCount, int Kpad) {
    constexpr int BM = 128;
    constexpr int BF = 8;                  // features per chunk -> 64 fp16 k
    constexpr int WN = BN / 2;
    constexpr int NA = WN / 8;
    constexpr int NPAIR = NA / 2;
    constexpr int A_BYTES = BM * 128;      // 16 KB
    constexpr int B_BYTES = BN * 128;      // 8 or 4 KB
    constexpr int BUF_STRIDE = A_BYTES + 2 * B_BYTES;
    constexpr int BITER = (BN * 8) / 256;  // B cp16 per thread (2 or 1)

    extern __shared__ char dynsmem[];
    uintptr_t tbase = ((uintptr_t)dynsmem + 1023) & ~(uintptr_t)1023;
    const uint32_t base0 = smem_u32((void*)tbase);

    const int tid = threadIdx.x;
    const int lane = tid & 31;
    const int wid = tid >> 5;
    const int warp_m = wid & 3;
    const int warp_n = wid >> 2;

    const int z = blockIdx.z;
    const int fBase = z * fCount;
    const int row0 = blockIdx.x * BM;
    const int col0 = blockIdx.y * BN;
    float* Cz = C + z * M * O;

    float acc[2][NA][4];
#pragma unroll
    for (int i = 0; i < 2; i++)
#pragma unroll
        for (int j = 0; j < NA; j++)
#pragma unroll
            for (int q = 0; q < 4; q++) acc[i][j][q] = 0.0f;

    const int Hout = 1 << hs;
    const int hwMask = (Hout * Hout) - 1;
    const int hwShift = 2 * hs;
    const int NC = fCount / BF;

    const uint32_t aRowOff = (uint32_t)(lane & 15) * 128 + ((uint32_t)(lane >> 4) << 4);
    const uint32_t bRowOff = ((uint32_t)((lane & 7) + ((lane >> 4) << 3))) * 128 +
                             (((uint32_t)(lane >> 3) & 1u) << 4);

    float pv[4];

    auto prefA = [&](int cc) {
#pragma unroll
        for (int it = 0; it < 4; it++) {
            const int l = tid + it * 256;
            const int mLocal = l & (BM - 1);
            const int fl = l >> 7;
            const int m = row0 + mLocal;
            const int f = fBase + cc * BF + fl;
            const int p = m & hwMask;
            const int b = m >> hwShift;
            const int ho = p >> hs, wo = p & (Hout - 1);
            const int c = f >> 4;
            const int r = f & 15;
            const int ih = 2 * ho + (r >> 2) - 1;
            const int iw = 2 * wo + (r & 3) - 1;
            float v = 0.0f;
            if ((unsigned)ih < (unsigned)Hin && (unsigned)iw < (unsigned)Hin) {
                int off = nchw
                    ? (((b * Cin + c) * Hin + ih) * Hin + iw)
                    : (((b * Hin + ih) * Hin + iw) * Cin + c);
                v = src[off];
                if (bns) v = fmaf(v, bns[c], bnt[c]);
            }
            pv[it] = v;
        }
    };
    auto issueB = [&](int cc) {
        const int buf = cc & 1;
        const uint32_t BH0 = base0 + buf * BUF_STRIDE + A_BYTES;
        const uint32_t BL0 = BH0 + B_BYTES;
        const int kG = (fBase + cc * BF) * 8;
#pragma unroll
        for (int it = 0; it < BITER; it++) {
            const int l = tid + it * 256;
            const int rown = l >> 3;
            const int cg = l & 7;
            const int gidx = (col0 + rown) * Kpad + kG + cg * 8;
            const uint32_t sw = sw128((uint32_t)(rown * 128 + cg * 16));
            cp16(BH0 + sw, Whi + gidx);
            cp16(BL0 + sw, Wlo + gidx);
        }
        cp_commit();
    };

    issueB(0);
    prefA(0);

    for (int cch = 0; cch < NC; cch++) {
        const int buf = cch & 1;
        const uint32_t A0 = base0 + buf * BUF_STRIDE;
        const uint32_t BH0 = A0 + A_BYTES;
        const uint32_t BL0 = BH0 + B_BYTES;

        // ---- expand + store A (registers -> smem) ----
#pragma unroll
        for (int it = 0; it < 4; it++) {
            const int l = tid + it * 256;
            const int mLocal = l & (BM - 1);
            const int fl = l >> 7;
            const float v = pv[it];
            float vals[6];
            vals[0] = fmaxf(v, 0.0f);
            spline5(v, &vals[1]);
            const uint32_t sw = sw128((uint32_t)(mLocal * 128 + fl * 16));
            sts128(A0 + sw, h2pack(vals[0], vals[1]), h2pack(vals[2], vals[3]),
                   h2pack(vals[4], vals[5]), 0u);
        }
        cp_wait<0>();        // B(cch) complete (only pending group)
        __syncthreads();     // A stores + B visible block-wide

        // ---- issue next chunk's loads; overlap with MMA below ----
        if (cch + 1 < NC) {
            issueB(cch + 1);   // writes buf(cch+1); its old readers done (sync above)
            prefA(cch + 1);
        }

        // ---- MMA: 4 K16 steps, 2 split terms ----
#pragma unroll
        for (int ks = 0; ks < 4; ks++) {
            const uint32_t kb = (uint32_t)(ks * 32);
            uint32_t ah[2][4];
#pragma unroll
            for (int am = 0; am < 2; am++) {
                const uint32_t off =
                    sw128((uint32_t)((warp_m * 32 + am * 16) * 128) + aRowOff + kb);
                ldsm_x4(ah[am], A0 + off);
            }
            uint32_t bh[NA][2], bl[NA][2];
#pragma unroll
            for (int pr = 0; pr < NPAIR; pr++) {
                const uint32_t off =
                    sw128((uint32_t)((warp_n * WN + pr * 16) * 128) + bRowOff + kb);
                uint32_t t[4];
                ldsm_x4(t, BH0 + off);
                bh[2 * pr][0] = t[0]; bh[2 * pr][1] = t[1];
                bh[2 * pr + 1][0] = t[2]; bh[2 * pr + 1][1] = t[3];
                ldsm_x4(t, BL0 + off);
                bl[2 * pr][0] = t[0]; bl[2 * pr][1] = t[1];
                bl[2 * pr + 1][0] = t[2]; bl[2 * pr + 1][1] = t[3];
            }
#pragma unroll
            for (int am = 0; am < 2; am++)
#pragma unroll
                for (int an = 0; an < NA; an++) {
                    mma16816(acc[am][an], ah[am], bh[an]);
                    mma16816(acc[am][an], ah[am], bl[an]);
                }
        }
        // no trailing sync: buffer written next is protected by next iteration's
        // sync (writer of buf X is always two syncs after buf X's last reader).
    }

    // ---- epilogue: write fragments ----
#pragma unroll
    for (int am = 0; am < 2; am++) {
        const int rr = row0 + warp_m * 32 + am * 16 + (lane >> 2);
#pragma unroll
        for (int an = 0; an < NA; an++) {
            const int cc = col0 + warp_n * WN + an * 8 + (lane & 3) * 2;
            *(float2*)&Cz[rr * O + cc] = make_float2(acc[am][an][0], acc[am][an][1]);
            *(float2*)&Cz[(rr + 8) * O + cc] = make_float2(acc[am][an][2], acc[am][an][3]);
        }
    }
}

// ---------------------------------------------------------------------------
// Split-K reduce (deterministic)
// ---------------------------------------------------------------------------
__global__ void reduce_splitk_kernel(const float* __restrict__ part,
                                     float* __restrict__ out, int MN, int S) {
    int idx = blockIdx.x * blockDim.x + threadIdx.x;
    if (idx >= MN) return;
    float a = 0.0f;
    for (int s = 0; s < S; s++) a += part[s * MN + idx];
    out[idx] = a;
}

// ---------------------------------------------------------------------------
// BN statistics -> fused affine y = x*s + t (double accum, deterministic).
// ---------------------------------------------------------------------------
__global__ void bnstats_kernel(const float* __restrict__ act,
                               const float* __restrict__ gamma,
                               const float* __restrict__ beta,
                               float* __restrict__ s_out,
                               float* __restrict__ t_out, int n, int C) {
    int c = blockIdx.x;
    double sum = 0.0, sum2 = 0.0;
    for (int e = threadIdx.x; e < n; e += blockDim.x) {
        float v = act[e * C + c];
        sum += v;
        sum2 += (double)v * v;
    }
    __shared__ double shs[256];
    __shared__ double sh2[256];
    shs[threadIdx.x] = sum;
    sh2[threadIdx.x] = sum2;
    __syncthreads();
    for (int o = 128; o > 0; o >>= 1) {
        if (threadIdx.x < o) {
            shs[threadIdx.x] += shs[threadIdx.x + o];
            sh2[threadIdx.x] += sh2[threadIdx.x + o];
        }
        __syncthreads();
    }
    if (threadIdx.x == 0) {
        double mean = shs[0] / n;
        double var = sh2[0] / n - mean * mean;
        double sv = (double)gamma[c] * rsqrt(var + 1e-5);
        s_out[c] = (float)sv;
        t_out[c] = (float)((double)beta[c] - mean * sv);
    }
}

// ---------------------------------------------------------------------------
// Head: BN3 affine + avgpool(2x2) + fc(128->1) + sigmoid.
// ---------------------------------------------------------------------------
__global__ void head_kernel(const float* __restrict__ act4,
                            const float* __restrict__ s,
                            const float* __restrict__ t,
                            const float* __restrict__ fcw,
                            const float* __restrict__ fcb,
                            float* __restrict__ out) {
    int b = blockIdx.x;
    int c = threadIdx.x;  // 128 threads
    const float* p = act4 + b * 4 * 128;
    float mval = 0.25f * (p[c] + p[128 + c] + p[256 + c] + p[384 + c]);
    float v = (s[c] * mval + t[c]) * fcw[c];
    __shared__ float sh[128];
    sh[c] = v;
    __syncthreads();
    for (int o = 64; o > 0; o >>= 1) {
        if (c < o) sh[c] += sh[c + o];
        __syncthreads();
    }
    if (c == 0) {
        float zv = sh[0] + fcb[0];
        out[b] = 1.0f / (1.0f + expf(-zv));
    }
}

// ---------------------------------------------------------------------------
// Launch
// ---------------------------------------------------------------------------
extern "C" void kernel_launch(void* const* d_in, const int* in_sizes, int n_in,
                              void* d_out, int out_size) {
    const float* x   = (const float*)d_in[0];
    const float* bw1 = (const float*)d_in[1];
    const float* sw1 = (const float*)d_in[2];
    const float* sc1 = (const float*)d_in[3];
    const float* bw2 = (const float*)d_in[4];
    const float* sw2 = (const float*)d_in[5];
    const float* sc2 = (const float*)d_in[6];
    const float* bw3 = (const float*)d_in[7];
    const float* sw3 = (const float*)d_in[8];
    const float* sc3 = (const float*)d_in[9];
    const float* bw4 = (const float*)d_in[10];
    const float* sw4 = (const float*)d_in[11];
    const float* sc4 = (const float*)d_in[12];
    const float* g1  = (const float*)d_in[13];
    const float* b1  = (const float*)d_in[14];
    const float* g2  = (const float*)d_in[15];
    const float* b2  = (const float*)d_in[16];
    const float* g3  = (const float*)d_in[17];
    const float* b3  = (const float*)d_in[18];
    const float* fcw = (const float*)d_in[19];
    const float* fcb = (const float*)d_in[20];
    float* out = (float*)d_out;

    __half *whi, *wlo;
    float *act1, *act2, *act3, *act4, *part;
    float *s1, *t1, *s2, *t2, *s3, *t3;
    cudaGetSymbolAddress((void**)&whi, g_Whi);
    cudaGetSymbolAddress((void**)&wlo, g_Wlo);
    cudaGetSymbolAddress((void**)&act1, g_act1);
    cudaGetSymbolAddress((void**)&act2, g_act2);
    cudaGetSymbolAddress((void**)&act3, g_act3);
    cudaGetSymbolAddress((void**)&act4, g_act4);
    cudaGetSymbolAddress((void**)&part, g_part);
    cudaGetSymbolAddress((void**)&s1, g_bnS1);
    cudaGetSymbolAddress((void**)&t1, g_bnT1);
    cudaGetSymbolAddress((void**)&s2, g_bnS2);
    cudaGetSymbolAddress((void**)&t2, g_bnT2);
    cudaGetSymbolAddress((void**)&s3, g_bnS3);
    cudaGetSymbolAddress((void**)&t3, g_bnT3);

    const int SMEM64 = 2 * (16384 + 2 * 64 * 128) + 1024;  // 66560
    const int SMEM32 = 2 * (16384 + 2 * 32 * 128) + 1024;  // 50176
    cudaFuncSetAttribute(kan_mma_kernel<32>,
                         cudaFuncAttributeMaxDynamicSharedMemorySize, SMEM32);
    cudaFuncSetAttribute(kan_mma_kernel<64>,
                         cudaFuncAttributeMaxDynamicSharedMemorySize, SMEM64);

    // ---- Layer 1: (512,3,32,32) NCHW -> (512,16,16,32) NHWC ----------------
    {
        const int F = 48, O = 32, M = 512 * 16 * 16, Kpad = 8 * F;
        build_wsplit_kernel<<<(O * Kpad + 255) / 256, 256>>>(bw1, sw1, sc1, whi, wlo, F, O, Kpad);
        kan_mma_kernel<32><<<dim3(M / 128, 1, 1), 256, SMEM32>>>(
            x, whi, wlo, act1, nullptr, nullptr, M, O, 3, 32, 4, 1, F, Kpad);
    }
    // ---- Layer 2: -> (512,8,8,64) via split2, BN1 stats ---------------------
    {
        const int F = 512, O = 64, M = 512 * 8 * 8, Kpad = 8 * F;
        const int SPLIT = 2;
        build_wsplit_kernel<<<(O * Kpad + 255) / 256, 256>>>(bw2, sw2, sc2, whi, wlo, F, O, Kpad);
        kan_mma_kernel<64><<<dim3(M / 128, 1, SPLIT), 256, SMEM64>>>(
            act1, whi, wlo, part, nullptr, nullptr, M, O, 32, 16, 3, 0, F / SPLIT, Kpad);
        reduce_splitk_kernel<<<(M * O + 255) / 256, 256>>>(part, act2, M * O, SPLIT);
        bnstats_kernel<<<64, 256>>>(act2, g1, b1, s1, t1, 512 * 64, 64);
    }
    // ---- Layer 3: BN1 fused -> (512,4,4,128) via split4, BN2 stats ----------
    {
        const int F = 1024, O = 128, M = 512 * 4 * 4, Kpad = 8 * F;
        const int SPLIT = 4;
        build_wsplit_kernel<<<(O * Kpad + 255) / 256, 256>>>(bw3, sw3, sc3, whi, wlo, F, O, Kpad);
        kan_mma_kernel<64><<<dim3(M / 128, O / 64, SPLIT), 256, SMEM64>>>(
            act2, whi, wlo, part, s1, t1, M, O, 64, 8, 2, 0, F / SPLIT, Kpad);
        reduce_splitk_kernel<<<(M * O + 255) / 256, 256>>>(part, act3, M * O, SPLIT);
        bnstats_kernel<<<128, 256>>>(act3, g2, b2, s2, t2, 512 * 16, 128);
    }
    // ---- Layer 4: BN2 fused -> (512,2,2,128) via split8, BN3 stats ----------
    {
        const int F = 2048, O = 128, M = 512 * 2 * 2, Kpad = 8 * F;
        const int SPLIT = 8;
        build_wsplit_kernel<<<(O * Kpad + 255) / 256, 256>>>(bw4, sw4, sc4, whi, wlo, F, O, Kpad);
        kan_mma_kernel<64><<<dim3(M / 128, O / 64, SPLIT), 256, SMEM64>>>(
            act3, whi, wlo, part, s2, t2, M, O, 128, 4, 1, 0, F / SPLIT, Kpad);
        reduce_splitk_kernel<<<(M * O + 255) / 256, 256>>>(part, act4, M * O, SPLIT);
        bnstats_kernel<<<128, 256>>>(act4, g3, b3, s3, t3, 512 * 4, 128);
    }
    // ---- Head --------------------------------------------------------------
    head_kernel<<<512, 128>>>(act4, s3, t3, fcw, fcb, out);
}

// round 10
// speedup vs baseline: 4.6596x; 1.2581x over previous
#include <cuda_runtime.h>
#include <cuda_fp16.h>
#include <math.h>
#include <stdint.h>

// ---------------------------------------------------------------------------
// Scratch (device globals; allocation-free). ~42 MB total.
// ---------------------------------------------------------------------------
__device__ __align__(16) __half g_Whi[2097152];  // [O][Kpad] hi, max 128x16384
__device__ __align__(16) __half g_Wlo[2097152];  // [O][Kpad] lo
__device__ float g_act1[4194304];     // (512,16,16,32) NHWC
__device__ float g_act2[2097152];     // (512,8,8,64)   NHWC
__device__ float g_act3[1048576];     // (512,4,4,128)  NHWC
__device__ float g_act4[262144];      // (512,2,2,128)  NHWC
__device__ float g_part[4194304];     // split-K partials
__device__ float g_bnS1[64],  g_bnT1[64];
__device__ float g_bnS2[128], g_bnT2[128];
__device__ float g_bnS3[128], g_bnT3[128];

// ---------------------------------------------------------------------------
// Helpers
// ---------------------------------------------------------------------------
__device__ __forceinline__ uint32_t smem_u32(const void* p) {
    uint32_t a;
    asm("{ .reg .u64 t; cvta.to.shared.u64 t, %1; cvt.u32.u64 %0, t; }"
        : "=r"(a) : "l"(p));
    return a;
}
__device__ __forceinline__ uint32_t sw128(uint32_t off) {
    return off ^ ((off >> 3) & 0x70);
}
__device__ __forceinline__ void sts128(uint32_t addr, uint32_t a, uint32_t b,
                                       uint32_t c, uint32_t d) {
    asm volatile("st.shared.v4.b32 [%0], {%1, %2, %3, %4};"
                 :: "r"(addr), "r"(a), "r"(b), "r"(c), "r"(d) : "memory");
}
__device__ __forceinline__ void cp16(uint32_t dst, const void* src) {
    asm volatile("cp.async.cg.shared.global [%0], [%1], 16;"
                 :: "r"(dst), "l"(src) : "memory");
}
__device__ __forceinline__ void cp_commit() {
    asm volatile("cp.async.commit_group;" ::: "memory");
}
template <int N>
__device__ __forceinline__ void cp_wait() {
    asm volatile("cp.async.wait_group %0;" :: "n"(N) : "memory");
}
__device__ __forceinline__ void ldsm_x4(uint32_t* r, uint32_t addr) {
    asm volatile("ldmatrix.sync.aligned.m8n8.x4.shared.b16 {%0,%1,%2,%3}, [%4];"
                 : "=r"(r[0]), "=r"(r[1]), "=r"(r[2]), "=r"(r[3]) : "r"(addr));
}
__device__ __forceinline__ void mma16816(float* c, const uint32_t* a, const uint32_t* b) {
    asm volatile(
        "mma.sync.aligned.m16n8k16.row.col.f32.f16.f16.f32 "
        "{%0,%1,%2,%3}, {%4,%5,%6,%7}, {%8,%9}, {%0,%1,%2,%3};"
        : "+f"(c[0]), "+f"(c[1]), "+f"(c[2]), "+f"(c[3])
        : "r"(a[0]), "r"(a[1]), "r"(a[2]), "r"(a[3]), "r"(b[0]), "r"(b[1]));
}
__device__ __forceinline__ uint32_t h2pack(float a, float b) {
    __half2 h = __floats2half2_rn(a, b);
    return *reinterpret_cast<uint32_t*>(&h);
}

// ---------------------------------------------------------------------------
// Closed-form quadratic B-spline (grid_size=3, order=2, uniform knots).
// ---------------------------------------------------------------------------
__device__ __forceinline__ void spline5(float x, float* bo) {
    float u = (x + 7.0f / 3.0f) * 1.5f;
    float fi = floorf(u);
    int i = (int)fi;
    float t = u - fi;
    float omt = 1.0f - t;
    float q0 = 0.5f * omt * omt;
    float q2 = 0.5f * t * t;
    float q1 = 1.0f - q0 - q2;
#pragma unroll
    for (int j = 0; j < 5; j++) {
        float v = 0.0f;
        v = (j == i - 2) ? q0 : v;
        v = (j == i - 1) ? q1 : v;
        v = (j == i)     ? q2 : v;
        bo[j] = v;
    }
}

// ---------------------------------------------------------------------------
// Build split weights (fp16 hi/lo): W[o][k], k = f*8 + t.
// corder=0: f is the source feature index (c*16+r).
// corder=1: f = r*Cin + c (window-major) -> source index fsrc = c*16 + r.
// ---------------------------------------------------------------------------
__global__ void build_wsplit_kernel(const float* __restrict__ bw,
                                    const float* __restrict__ sw,
                                    const float* __restrict__ sc,
                                    __half* __restrict__ whi,
                                    __half* __restrict__ wlo,
                                    int F, int O, int Kpad, int corder, int Cin) {
    int idx = blockIdx.x * blockDim.x + threadIdx.x;
    if (idx >= O * Kpad) return;
    int o = idx / Kpad;
    int k = idx % Kpad;
    int f = k >> 3;
    int t = k & 7;
    int fsrc = f;
    if (corder) {
        int r = f / Cin;
        int c = f - r * Cin;
        fsrc = c * 16 + r;
    }
    float val = 0.0f;
    if (t == 0)      val = bw[o * F + fsrc];
    else if (t <= 5) val = sw[(o * F + fsrc) * 5 + (t - 1)] * sc[o * F + fsrc];
    __half h = __float2half_rn(val);
    __half l = __float2half_rn(val - __half2float(h));
    whi[idx] = h;
    wlo[idx] = l;
}

// ---------------------------------------------------------------------------
// Fused KAN-conv GEMM on mma.sync (fp16 A, fp16 W hi/lo 2-term, fp32 accum).
// BM=128 x BN, 8 warps (4M x 2N). Double-buffered chunks; A gathered with
// the coalesced window-major ordering (corder=1) or legacy scatter (corder=0);
// B via cp.async. One __syncthreads per chunk. grid.z splits the K range.
// ---------------------------------------------------------------------------
template <int BN>
__global__ __launch_bounds__(256, 3)
void kan_mma_kernel(const float* __restrict__ src,
                    const __half* __restrict__ Whi,
                    const __half* __restrict__ Wlo,
                    float* __restrict__ C,
                    const float* __restrict__ bns,
                    const float* __restrict__ bnt,
                    int M, int O, int Cin, int Hin, int hs, int nchw,
                    int fCount, int Kpad, int corder, int cinShift) {
    constexpr int BM = 128;
    constexpr int BF = 8;
    constexpr int WN = BN / 2;
    constexpr int NA = WN / 8;
    constexpr int NPAIR = NA / 2;
    constexpr int A_BYTES = BM * 128;
    constexpr int B_BYTES = BN * 128;
    constexpr int BUF_STRIDE = A_BYTES + 2 * B_BYTES;
    constexpr int BITER = (BN * 8) / 256;

    extern __shared__ char dynsmem[];
    uintptr_t tbase = ((uintptr_t)dynsmem + 1023) & ~(uintptr_t)1023;
    const uint32_t base0 = smem_u32((void*)tbase);

    const int tid = threadIdx.x;
    const int lane = tid & 31;
    const int wid = tid >> 5;
    const int warp_m = wid & 3;
    const int warp_n = wid >> 2;

    const int z = blockIdx.z;
    const int fBase = z * fCount;
    const int row0 = blockIdx.x * BM;
    const int col0 = blockIdx.y * BN;
    float* Cz = C + z * M * O;

    float acc[2][NA][4];
#pragma unroll
    for (int i = 0; i < 2; i++)
#pragma unroll
        for (int j = 0; j < NA; j++)
#pragma unroll
            for (int q = 0; q < 4; q++) acc[i][j][q] = 0.0f;

    const int Hout = 1 << hs;
    const int hwMask = (Hout * Hout) - 1;
    const int hwShift = 2 * hs;
    const int NC = fCount / BF;

    const uint32_t aRowOff = (uint32_t)(lane & 15) * 128 + ((uint32_t)(lane >> 4) << 4);
    const uint32_t bRowOff = ((uint32_t)((lane & 7) + ((lane >> 4) << 3))) * 128 +
                             (((uint32_t)(lane >> 3) & 1u) << 4);

    float pv[4];

    // ---- coalesced-path per-thread constants (corder=1) ----
    // l = tid + it*256; c_off = l & 7 (same for all it); mLocal = l >> 3.
    const int c_off = tid & 7;

    auto prefA = [&](int cc) {
        if (corder) {
            const int fc = fBase + cc * BF;          // chunk start (uniform)
            const int r = fc >> cinShift;            // fixed window pos
            const int c = (fc - (r << cinShift)) + c_off;
            const int wi = r >> 2, wj = r & 3;
#pragma unroll
            for (int it = 0; it < 4; it++) {
                const int mLocal = (tid >> 3) + it * 32;
                const int m = row0 + mLocal;
                const int p = m & hwMask;
                const int b = m >> hwShift;
                const int ho = p >> hs, wo = p & (Hout - 1);
                const int ih = 2 * ho + wi - 1;
                const int iw = 2 * wo + wj - 1;
                float v = 0.0f;
                if ((unsigned)ih < (unsigned)Hin && (unsigned)iw < (unsigned)Hin) {
                    const int off = (((b * Hin + ih) * Hin + iw) << cinShift) + c;
                    v = src[off];
                    if (bns) v = fmaf(v, bns[c], bnt[c]);
                }
                pv[it] = v;
            }
        } else {
#pragma unroll
            for (int it = 0; it < 4; it++) {
                const int l = tid + it * 256;
                const int mLocal = l & (BM - 1);
                const int fl = l >> 7;
                const int m = row0 + mLocal;
                const int f = fBase + cc * BF + fl;
                const int p = m & hwMask;
                const int b = m >> hwShift;
                const int ho = p >> hs, wo = p & (Hout - 1);
                const int c = f >> 4;
                const int r = f & 15;
                const int ih = 2 * ho + (r >> 2) - 1;
                const int iw = 2 * wo + (r & 3) - 1;
                float v = 0.0f;
                if ((unsigned)ih < (unsigned)Hin && (unsigned)iw < (unsigned)Hin) {
                    int off = nchw
                        ? (((b * Cin + c) * Hin + ih) * Hin + iw)
                        : (((b * Hin + ih) * Hin + iw) * Cin + c);
                    v = src[off];
                    if (bns) v = fmaf(v, bns[c], bnt[c]);
                }
                pv[it] = v;
            }
        }
    };
    auto issueB = [&](int cc) {
        const int buf = cc & 1;
        const uint32_t BH0 = base0 + buf * BUF_STRIDE + A_BYTES;
        const uint32_t BL0 = BH0 + B_BYTES;
        const int kG = (fBase + cc * BF) * 8;
#pragma unroll
        for (int it = 0; it < BITER; it++) {
            const int l = tid + it * 256;
            const int rown = l >> 3;
            const int cg = l & 7;
            const int gidx = (col0 + rown) * Kpad + kG + cg * 8;
            const uint32_t sw = sw128((uint32_t)(rown * 128 + cg * 16));
            cp16(BH0 + sw, Whi + gidx);
            cp16(BL0 + sw, Wlo + gidx);
        }
        cp_commit();
    };

    issueB(0);
    prefA(0);

    for (int cch = 0; cch < NC; cch++) {
        const int buf = cch & 1;
        const uint32_t A0 = base0 + buf * BUF_STRIDE;
        const uint32_t BH0 = A0 + A_BYTES;
        const uint32_t BL0 = BH0 + B_BYTES;

        // ---- expand + store A ----
#pragma unroll
        for (int it = 0; it < 4; it++) {
            const int mLocal = corder ? ((tid >> 3) + it * 32)
                                      : ((tid + it * 256) & (BM - 1));
            const int fl = corder ? c_off : ((tid + it * 256) >> 7);
            const float v = pv[it];
            float vals[6];
            vals[0] = fmaxf(v, 0.0f);
            spline5(v, &vals[1]);
            const uint32_t sw = sw128((uint32_t)(mLocal * 128 + fl * 16));
            sts128(A0 + sw, h2pack(vals[0], vals[1]), h2pack(vals[2], vals[3]),
                   h2pack(vals[4], vals[5]), 0u);
        }
        cp_wait<0>();
        __syncthreads();

        if (cch + 1 < NC) {
            issueB(cch + 1);
            prefA(cch + 1);
        }

        // ---- MMA: 4 K16 steps, 2 split terms ----
#pragma unroll
        for (int ks = 0; ks < 4; ks++) {
            const uint32_t kb = (uint32_t)(ks * 32);
            uint32_t ah[2][4];
#pragma unroll
            for (int am = 0; am < 2; am++) {
                const uint32_t off =
                    sw128((uint32_t)((warp_m * 32 + am * 16) * 128) + aRowOff + kb);
                ldsm_x4(ah[am], A0 + off);
            }
            uint32_t bh[NA][2], bl[NA][2];
#pragma unroll
            for (int pr = 0; pr < NPAIR; pr++) {
                const uint32_t off =
                    sw128((uint32_t)((warp_n * WN + pr * 16) * 128) + bRowOff + kb);
                uint32_t t[4];
                ldsm_x4(t, BH0 + off);
                bh[2 * pr][0] = t[0]; bh[2 * pr][1] = t[1];
                bh[2 * pr + 1][0] = t[2]; bh[2 * pr + 1][1] = t[3];
                ldsm_x4(t, BL0 + off);
                bl[2 * pr][0] = t[0]; bl[2 * pr][1] = t[1];
                bl[2 * pr + 1][0] = t[2]; bl[2 * pr + 1][1] = t[3];
            }
#pragma unroll
            for (int am = 0; am < 2; am++)
#pragma unroll
                for (int an = 0; an < NA; an++) {
                    mma16816(acc[am][an], ah[am], bh[an]);
                    mma16816(acc[am][an], ah[am], bl[an]);
                }
        }
    }

    // ---- epilogue ----
#pragma unroll
    for (int am = 0; am < 2; am++) {
        const int rr = row0 + warp_m * 32 + am * 16 + (lane >> 2);
#pragma unroll
        for (int an = 0; an < NA; an++) {
            const int cc = col0 + warp_n * WN + an * 8 + (lane & 3) * 2;
            *(float2*)&Cz[rr * O + cc] = make_float2(acc[am][an][0], acc[am][an][1]);
            *(float2*)&Cz[(rr + 8) * O + cc] = make_float2(acc[am][an][2], acc[am][an][3]);
        }
    }
}

// ---------------------------------------------------------------------------
// Split-K reduce (deterministic)
// ---------------------------------------------------------------------------
__global__ void reduce_splitk_kernel(const float* __restrict__ part,
                                     float* __restrict__ out, int MN, int S) {
    int idx = blockIdx.x * blockDim.x + threadIdx.x;
    if (idx >= MN) return;
    float a = 0.0f;
    for (int s = 0; s < S; s++) a += part[s * MN + idx];
    out[idx] = a;
}

// ---------------------------------------------------------------------------
// BN statistics -> fused affine y = x*s + t (double accum, deterministic).
// ---------------------------------------------------------------------------
__global__ void bnstats_kernel(const float* __restrict__ act,
                               const float* __restrict__ gamma,
                               const float* __restrict__ beta,
                               float* __restrict__ s_out,
                               float* __restrict__ t_out, int n, int C) {
    int c = blockIdx.x;
    double sum = 0.0, sum2 = 0.0;
    for (int e = threadIdx.x; e < n; e += blockDim.x) {
        float v = act[e * C + c];
        sum += v;
        sum2 += (double)v * v;
    }
    __shared__ double shs[256];
    __shared__ double sh2[256];
    shs[threadIdx.x] = sum;
    sh2[threadIdx.x] = sum2;
    __syncthreads();
    for (int o = 128; o > 0; o >>= 1) {
        if (threadIdx.x < o) {
            shs[threadIdx.x] += shs[threadIdx.x + o];
            sh2[threadIdx.x] += sh2[threadIdx.x + o];
        }
        __syncthreads();
    }
    if (threadIdx.x == 0) {
        double mean = shs[0] / n;
        double var = sh2[0] / n - mean * mean;
        double sv = (double)gamma[c] * rsqrt(var + 1e-5);
        s_out[c] = (float)sv;
        t_out[c] = (float)((double)beta[c] - mean * sv);
    }
}

// ---------------------------------------------------------------------------
// Head: BN3 affine + avgpool(2x2) + fc(128->1) + sigmoid.
// ---------------------------------------------------------------------------
__global__ void head_kernel(const float* __restrict__ act4,
                            const float* __restrict__ s,
                            const float* __restrict__ t,
                            const float* __restrict__ fcw,
                            const float* __restrict__ fcb,
                            float* __restrict__ out) {
    int b = blockIdx.x;
    int c = threadIdx.x;
    const float* p = act4 + b * 4 * 128;
    float mval = 0.25f * (p[c] + p[128 + c] + p[256 + c] + p[384 + c]);
    float v = (s[c] * mval + t[c]) * fcw[c];
    __shared__ float sh[128];
    sh[c] = v;
    __syncthreads();
    for (int o = 64; o > 0; o >>= 1) {
        if (c < o) sh[c] += sh[c + o];
        __syncthreads();
    }
    if (c == 0) {
        float zv = sh[0] + fcb[0];
        out[b] = 1.0f / (1.0f + expf(-zv));
    }
}

// ---------------------------------------------------------------------------
// Launch
// ---------------------------------------------------------------------------
extern "C" void kernel_launch(void* const* d_in, const int* in_sizes, int n_in,
                              void* d_out, int out_size) {
    const float* x   = (const float*)d_in[0];
    const float* bw1 = (const float*)d_in[1];
    const float* sw1 = (const float*)d_in[2];
    const float* sc1 = (const float*)d_in[3];
    const float* bw2 = (const float*)d_in[4];
    const float* sw2 = (const float*)d_in[5];
    const float* sc2 = (const float*)d_in[6];
    const float* bw3 = (const float*)d_in[7];
    const float* sw3 = (const float*)d_in[8];
    const float* sc3 = (const float*)d_in[9];
    const float* bw4 = (const float*)d_in[10];
    const float* sw4 = (const float*)d_in[11];
    const float* sc4 = (const float*)d_in[12];
    const float* g1  = (const float*)d_in[13];
    const float* b1  = (const float*)d_in[14];
    const float* g2  = (const float*)d_in[15];
    const float* b2  = (const float*)d_in[16];
    const float* g3  = (const float*)d_in[17];
    const float* b3  = (const float*)d_in[18];
    const float* fcw = (const float*)d_in[19];
    const float* fcb = (const float*)d_in[20];
    float* out = (float*)d_out;

    __half *whi, *wlo;
    float *act1, *act2, *act3, *act4, *part;
    float *s1, *t1, *s2, *t2, *s3, *t3;
    cudaGetSymbolAddress((void**)&whi, g_Whi);
    cudaGetSymbolAddress((void**)&wlo, g_Wlo);
    cudaGetSymbolAddress((void**)&act1, g_act1);
    cudaGetSymbolAddress((void**)&act2, g_act2);
    cudaGetSymbolAddress((void**)&act3, g_act3);
    cudaGetSymbolAddress((void**)&act4, g_act4);
    cudaGetSymbolAddress((void**)&part, g_part);
    cudaGetSymbolAddress((void**)&s1, g_bnS1);
    cudaGetSymbolAddress((void**)&t1, g_bnT1);
    cudaGetSymbolAddress((void**)&s2, g_bnS2);
    cudaGetSymbolAddress((void**)&t2, g_bnT2);
    cudaGetSymbolAddress((void**)&s3, g_bnS3);
    cudaGetSymbolAddress((void**)&t3, g_bnT3);

    const int SMEM64 = 2 * (16384 + 2 * 64 * 128) + 1024;
    const int SMEM32 = 2 * (16384 + 2 * 32 * 128) + 1024;
    cudaFuncSetAttribute(kan_mma_kernel<32>,
                         cudaFuncAttributeMaxDynamicSharedMemorySize, SMEM32);
    cudaFuncSetAttribute(kan_mma_kernel<64>,
                         cudaFuncAttributeMaxDynamicSharedMemorySize, SMEM64);

    // ---- Layer 1: (512,3,32,32) NCHW -> (512,16,16,32) NHWC (legacy order) --
    {
        const int F = 48, O = 32, M = 512 * 16 * 16, Kpad = 8 * F;
        build_wsplit_kernel<<<(O * Kpad + 255) / 256, 256>>>(
            bw1, sw1, sc1, whi, wlo, F, O, Kpad, 0, 3);
        kan_mma_kernel<32><<<dim3(M / 128, 1, 1), 256, SMEM32>>>(
            x, whi, wlo, act1, nullptr, nullptr, M, O, 3, 32, 4, 1, F, Kpad, 0, 0);
    }
    // ---- Layer 2: -> (512,8,8,64) via split2, coalesced order ---------------
    {
        const int F = 512, O = 64, M = 512 * 8 * 8, Kpad = 8 * F;
        const int SPLIT = 2;
        build_wsplit_kernel<<<(O * Kpad + 255) / 256, 256>>>(
            bw2, sw2, sc2, whi, wlo, F, O, Kpad, 1, 32);
        kan_mma_kernel<64><<<dim3(M / 128, 1, SPLIT), 256, SMEM64>>>(
            act1, whi, wlo, part, nullptr, nullptr, M, O, 32, 16, 3, 0,
            F / SPLIT, Kpad, 1, 5);
        reduce_splitk_kernel<<<(M * O + 255) / 256, 256>>>(part, act2, M * O, SPLIT);
        bnstats_kernel<<<64, 256>>>(act2, g1, b1, s1, t1, 512 * 64, 64);
    }
    // ---- Layer 3: BN1 fused -> (512,4,4,128) via split4 ---------------------
    {
        const int F = 1024, O = 128, M = 512 * 4 * 4, Kpad = 8 * F;
        const int SPLIT = 4;
        build_wsplit_kernel<<<(O * Kpad + 255) / 256, 256>>>(
            bw3, sw3, sc3, whi, wlo, F, O, Kpad, 1, 64);
        kan_mma_kernel<64><<<dim3(M / 128, O / 64, SPLIT), 256, SMEM64>>>(
            act2, whi, wlo, part, s1, t1, M, O, 64, 8, 2, 0, F / SPLIT, Kpad, 1, 6);
        reduce_splitk_kernel<<<(M * O + 255) / 256, 256>>>(part, act3, M * O, SPLIT);
        bnstats_kernel<<<128, 256>>>(act3, g2, b2, s2, t2, 512 * 16, 128);
    }
    // ---- Layer 4: BN2 fused -> (512,2,2,128) via split8 ---------------------
    {
        const int F = 2048, O = 128, M = 512 * 2 * 2, Kpad = 8 * F;
        const int SPLIT = 8;
        build_wsplit_kernel<<<(O * Kpad + 255) / 256, 256>>>(
            bw4, sw4, sc4, whi, wlo, F, O, Kpad, 1, 128);
        kan_mma_kernel<64><<<dim3(M / 128, O / 64, SPLIT), 256, SMEM64>>>(
            act3, whi, wlo, part, s2, t2, M, O, 128, 4, 1, 0, F / SPLIT, Kpad, 1, 7);
        reduce_splitk_kernel<<<(M * O + 255) / 256, 256>>>(part, act4, M * O, SPLIT);
        bnstats_kernel<<<128, 256>>>(act4, g3, b3, s3, t3, 512 * 4, 128);
    }
    // ---- Head --------------------------------------------------------------
    head_kernel<<<512, 128>>>(act4, s3, t3, fcw, fcb, out);
}

// round 11
// speedup vs baseline: 4.8704x; 1.0452x over previous
#include <cuda_runtime.h>
#include <cuda_fp16.h>
#include <math.h>
#include <stdint.h>

// ---------------------------------------------------------------------------
// Scratch (device globals; allocation-free). ~30 MB total.
// ---------------------------------------------------------------------------
__device__ __align__(16) __half g_Whi[2097152];  // [O][Kpad] hi, max 128x16384
__device__ __align__(16) __half g_Wlo[2097152];  // [O][Kpad] lo
__device__ __align__(16) __half g_act1[4194304]; // (512,16,16,32) NHWC fp16
__device__ __align__(16) __half g_act2[2097152]; // (512,8,8,64)   NHWC fp16
__device__ __align__(16) __half g_act3[1048576]; // (512,4,4,128)  NHWC fp16
__device__ __align__(16) __half g_act4[262144];  // (512,2,2,128)  NHWC fp16
__device__ float g_part[4194304];     // split-K fp32 partials (16 MB)
__device__ float g_bnS1[64],  g_bnT1[64];
__device__ float g_bnS2[128], g_bnT2[128];
__device__ float g_bnS3[128], g_bnT3[128];

// ---------------------------------------------------------------------------
// Helpers
// ---------------------------------------------------------------------------
__device__ __forceinline__ uint32_t smem_u32(const void* p) {
    uint32_t a;
    asm("{ .reg .u64 t; cvta.to.shared.u64 t, %1; cvt.u32.u64 %0, t; }"
        : "=r"(a) : "l"(p));
    return a;
}
__device__ __forceinline__ uint32_t sw128(uint32_t off) {
    return off ^ ((off >> 3) & 0x70);
}
__device__ __forceinline__ void sts128(uint32_t addr, uint32_t a, uint32_t b,
                                       uint32_t c, uint32_t d) {
    asm volatile("st.shared.v4.b32 [%0], {%1, %2, %3, %4};"
                 :: "r"(addr), "r"(a), "r"(b), "r"(c), "r"(d) : "memory");
}
__device__ __forceinline__ void cp16(uint32_t dst, const void* src) {
    asm volatile("cp.async.cg.shared.global [%0], [%1], 16;"
                 :: "r"(dst), "l"(src) : "memory");
}
__device__ __forceinline__ void cp_commit() {
    asm volatile("cp.async.commit_group;" ::: "memory");
}
template <int N>
__device__ __forceinline__ void cp_wait() {
    asm volatile("cp.async.wait_group %0;" :: "n"(N) : "memory");
}
__device__ __forceinline__ void ldsm_x4(uint32_t* r, uint32_t addr) {
    asm volatile("ldmatrix.sync.aligned.m8n8.x4.shared.b16 {%0,%1,%2,%3}, [%4];"
                 : "=r"(r[0]), "=r"(r[1]), "=r"(r[2]), "=r"(r[3]) : "r"(addr));
}
__device__ __forceinline__ void mma16816(float* c, const uint32_t* a, const uint32_t* b) {
    asm volatile(
        "mma.sync.aligned.m16n8k16.row.col.f32.f16.f16.f32 "
        "{%0,%1,%2,%3}, {%4,%5,%6,%7}, {%8,%9}, {%0,%1,%2,%3};"
        : "+f"(c[0]), "+f"(c[1]), "+f"(c[2]), "+f"(c[3])
        : "r"(a[0]), "r"(a[1]), "r"(a[2]), "r"(a[3]), "r"(b[0]), "r"(b[1]));
}
__device__ __forceinline__ uint32_t h2pack(float a, float b) {
    __half2 h = __floats2half2_rn(a, b);
    return *reinterpret_cast<uint32_t*>(&h);
}
__device__ __forceinline__ float ldval(const float* p, int off) { return p[off]; }
__device__ __forceinline__ float ldval(const __half* p, int off) {
    return __half2float(p[off]);
}

// ---------------------------------------------------------------------------
// Closed-form quadratic B-spline (grid_size=3, order=2, uniform knots).
// ---------------------------------------------------------------------------
__device__ __forceinline__ void spline5(float x, float* bo) {
    float u = (x + 7.0f / 3.0f) * 1.5f;
    float fi = floorf(u);
    int i = (int)fi;
    float t = u - fi;
    float omt = 1.0f - t;
    float q0 = 0.5f * omt * omt;
    float q2 = 0.5f * t * t;
    float q1 = 1.0f - q0 - q2;
#pragma unroll
    for (int j = 0; j < 5; j++) {
        float v = 0.0f;
        v = (j == i - 2) ? q0 : v;
        v = (j == i - 1) ? q1 : v;
        v = (j == i)     ? q2 : v;
        bo[j] = v;
    }
}

// ---------------------------------------------------------------------------
// Build split weights (fp16 hi/lo): W[o][k], k = f*8 + t.
// corder=1: f = r*Cin + c (window-major) -> source index fsrc = c*16 + r.
// ---------------------------------------------------------------------------
__global__ void build_wsplit_kernel(const float* __restrict__ bw,
                                    const float* __restrict__ sw,
                                    const float* __restrict__ sc,
                                    __half* __restrict__ whi,
                                    __half* __restrict__ wlo,
                                    int F, int O, int Kpad, int corder, int Cin) {
    int idx = blockIdx.x * blockDim.x + threadIdx.x;
    if (idx >= O * Kpad) return;
    int o = idx / Kpad;
    int k = idx % Kpad;
    int f = k >> 3;
    int t = k & 7;
    int fsrc = f;
    if (corder) {
        int r = f / Cin;
        int c = f - r * Cin;
        fsrc = c * 16 + r;
    }
    float val = 0.0f;
    if (t == 0)      val = bw[o * F + fsrc];
    else if (t <= 5) val = sw[(o * F + fsrc) * 5 + (t - 1)] * sc[o * F + fsrc];
    __half h = __float2half_rn(val);
    __half l = __float2half_rn(val - __half2float(h));
    whi[idx] = h;
    wlo[idx] = l;
}

// ---------------------------------------------------------------------------
// Fused KAN-conv GEMM on mma.sync (fp16 A, fp16 W hi/lo 2-term, fp32 accum).
// BM=128 x BN, 8 warps (4M x 2N). Double-buffered chunks; coalesced
// window-major gather (corder=1) or legacy scatter (corder=0, layer 1).
// Writes fp32 partials; grid.z splits the K range.
// ---------------------------------------------------------------------------
template <int BN, typename T>
__global__ __launch_bounds__(256, 3)
void kan_mma_kernel(const T* __restrict__ src,
                    const __half* __restrict__ Whi,
                    const __half* __restrict__ Wlo,
                    float* __restrict__ C,
                    const float* __restrict__ bns,
                    const float* __restrict__ bnt,
                    int M, int O, int Cin, int Hin, int hs, int nchw,
                    int fCount, int Kpad, int corder, int cinShift) {
    constexpr int BM = 128;
    constexpr int BF = 8;
    constexpr int WN = BN / 2;
    constexpr int NA = WN / 8;
    constexpr int NPAIR = NA / 2;
    constexpr int A_BYTES = BM * 128;
    constexpr int B_BYTES = BN * 128;
    constexpr int BUF_STRIDE = A_BYTES + 2 * B_BYTES;
    constexpr int BITER = (BN * 8) / 256;

    extern __shared__ char dynsmem[];
    uintptr_t tbase = ((uintptr_t)dynsmem + 1023) & ~(uintptr_t)1023;
    const uint32_t base0 = smem_u32((void*)tbase);

    const int tid = threadIdx.x;
    const int lane = tid & 31;
    const int wid = tid >> 5;
    const int warp_m = wid & 3;
    const int warp_n = wid >> 2;

    const int z = blockIdx.z;
    const int fBase = z * fCount;
    const int row0 = blockIdx.x * BM;
    const int col0 = blockIdx.y * BN;
    float* Cz = C + z * M * O;

    float acc[2][NA][4];
#pragma unroll
    for (int i = 0; i < 2; i++)
#pragma unroll
        for (int j = 0; j < NA; j++)
#pragma unroll
            for (int q = 0; q < 4; q++) acc[i][j][q] = 0.0f;

    const int Hout = 1 << hs;
    const int hwMask = (Hout * Hout) - 1;
    const int hwShift = 2 * hs;
    const int NC = fCount / BF;

    const uint32_t aRowOff = (uint32_t)(lane & 15) * 128 + ((uint32_t)(lane >> 4) << 4);
    const uint32_t bRowOff = ((uint32_t)((lane & 7) + ((lane >> 4) << 3))) * 128 +
                             (((uint32_t)(lane >> 3) & 1u) << 4);
    // Pre-swizzled tile offsets; per-ks address = base + (off ^ kb).
    // (Valid because tile offsets have bits 5-6 clear, kb in {0,32,64,96}.)
    uint32_t aOffSw[2], bOffSw[NPAIR];
#pragma unroll
    for (int am = 0; am < 2; am++)
        aOffSw[am] = sw128((uint32_t)((warp_m * 32 + am * 16) * 128) + aRowOff);
#pragma unroll
    for (int pr = 0; pr < NPAIR; pr++)
        bOffSw[pr] = sw128((uint32_t)((warp_n * WN + pr * 16) * 128) + bRowOff);

    float pv[4];
    const int c_off = tid & 7;

    auto prefA = [&](int cc) {
        if (corder) {
            const int fc = fBase + cc * BF;
            const int r = fc >> cinShift;
            const int c = (fc - (r << cinShift)) + c_off;
            const int wi = r >> 2, wj = r & 3;
#pragma unroll
            for (int it = 0; it < 4; it++) {
                const int mLocal = (tid >> 3) + it * 32;
                const int m = row0 + mLocal;
                const int p = m & hwMask;
                const int b = m >> hwShift;
                const int ho = p >> hs, wo = p & (Hout - 1);
                const int ih = 2 * ho + wi - 1;
                const int iw = 2 * wo + wj - 1;
                float v = 0.0f;
                if ((unsigned)ih < (unsigned)Hin && (unsigned)iw < (unsigned)Hin) {
                    const int off = (((b * Hin + ih) * Hin + iw) << cinShift) + c;
                    v = ldval(src, off);
                    if (bns) v = fmaf(v, bns[c], bnt[c]);
                }
                pv[it] = v;
            }
        } else {
#pragma unroll
            for (int it = 0; it < 4; it++) {
                const int l = tid + it * 256;
                const int mLocal = l & (BM - 1);
                const int fl = l >> 7;
                const int m = row0 + mLocal;
                const int f = fBase + cc * BF + fl;
                const int p = m & hwMask;
                const int b = m >> hwShift;
                const int ho = p >> hs, wo = p & (Hout - 1);
                const int c = f >> 4;
                const int r = f & 15;
                const int ih = 2 * ho + (r >> 2) - 1;
                const int iw = 2 * wo + (r & 3) - 1;
                float v = 0.0f;
                if ((unsigned)ih < (unsigned)Hin && (unsigned)iw < (unsigned)Hin) {
                    int off = nchw
                        ? (((b * Cin + c) * Hin + ih) * Hin + iw)
                        : (((b * Hin + ih) * Hin + iw) * Cin + c);
                    v = ldval(src, off);
                    if (bns) v = fmaf(v, bns[c], bnt[c]);
                }
                pv[it] = v;
            }
        }
    };
    auto issueB = [&](int cc) {
        const int buf = cc & 1;
        const uint32_t BH0 = base0 + buf * BUF_STRIDE + A_BYTES;
        const uint32_t BL0 = BH0 + B_BYTES;
        const int kG = (fBase + cc * BF) * 8;
#pragma unroll
        for (int it = 0; it < BITER; it++) {
            const int l = tid + it * 256;
            const int rown = l >> 3;
            const int cg = l & 7;
            const int gidx = (col0 + rown) * Kpad + kG + cg * 8;
            const uint32_t sw = sw128((uint32_t)(rown * 128 + cg * 16));
            cp16(BH0 + sw, Whi + gidx);
            cp16(BL0 + sw, Wlo + gidx);
        }
        cp_commit();
    };

    issueB(0);
    prefA(0);

    for (int cch = 0; cch < NC; cch++) {
        const int buf = cch & 1;
        const uint32_t A0 = base0 + buf * BUF_STRIDE;
        const uint32_t BH0 = A0 + A_BYTES;
        const uint32_t BL0 = BH0 + B_BYTES;

        // ---- expand + store A ----
#pragma unroll
        for (int it = 0; it < 4; it++) {
            const int mLocal = corder ? ((tid >> 3) + it * 32)
                                      : ((tid + it * 256) & (BM - 1));
            const int fl = corder ? c_off : ((tid + it * 256) >> 7);
            const float v = pv[it];
            float vals[6];
            vals[0] = fmaxf(v, 0.0f);
            spline5(v, &vals[1]);
            const uint32_t sw = sw128((uint32_t)(mLocal * 128 + fl * 16));
            sts128(A0 + sw, h2pack(vals[0], vals[1]), h2pack(vals[2], vals[3]),
                   h2pack(vals[4], vals[5]), 0u);
        }
        cp_wait<0>();
        __syncthreads();

        if (cch + 1 < NC) {
            issueB(cch + 1);
            prefA(cch + 1);
        }

        // ---- MMA: 4 K16 steps, 2 split terms ----
#pragma unroll
        for (int ks = 0; ks < 4; ks++) {
            const uint32_t kb = (uint32_t)(ks * 32);
            uint32_t ah[2][4];
#pragma unroll
            for (int am = 0; am < 2; am++)
                ldsm_x4(ah[am], A0 + (aOffSw[am] ^ kb));
            uint32_t bh[NA][2], bl[NA][2];
#pragma unroll
            for (int pr = 0; pr < NPAIR; pr++) {
                uint32_t t[4];
                ldsm_x4(t, BH0 + (bOffSw[pr] ^ kb));
                bh[2 * pr][0] = t[0]; bh[2 * pr][1] = t[1];
                bh[2 * pr + 1][0] = t[2]; bh[2 * pr + 1][1] = t[3];
                ldsm_x4(t, BL0 + (bOffSw[pr] ^ kb));
                bl[2 * pr][0] = t[0]; bl[2 * pr][1] = t[1];
                bl[2 * pr + 1][0] = t[2]; bl[2 * pr + 1][1] = t[3];
            }
#pragma unroll
            for (int am = 0; am < 2; am++)
#pragma unroll
                for (int an = 0; an < NA; an++) {
                    mma16816(acc[am][an], ah[am], bh[an]);
                    mma16816(acc[am][an], ah[am], bl[an]);
                }
        }
    }

    // ---- epilogue: fp32 partials ----
#pragma unroll
    for (int am = 0; am < 2; am++) {
        const int rr = row0 + warp_m * 32 + am * 16 + (lane >> 2);
#pragma unroll
        for (int an = 0; an < NA; an++) {
            const int cc = col0 + warp_n * WN + an * 8 + (lane & 3) * 2;
            *(float2*)&Cz[rr * O + cc] = make_float2(acc[am][an][0], acc[am][an][1]);
            *(float2*)&Cz[(rr + 8) * O + cc] = make_float2(acc[am][an][2], acc[am][an][3]);
        }
    }
}

// ---------------------------------------------------------------------------
// Split-K reduce -> fp16 activation (deterministic)
// ---------------------------------------------------------------------------
__global__ void reduce_splitk_kernel(const float* __restrict__ part,
                                     __half* __restrict__ out, int MN, int S) {
    int idx = blockIdx.x * blockDim.x + threadIdx.x;
    if (idx >= MN) return;
    float a = 0.0f;
    for (int s = 0; s < S; s++) a += part[s * MN + idx];
    out[idx] = __float2half_rn(a);
}

// ---------------------------------------------------------------------------
// BN statistics on fp16 activations -> fused affine y = x*s + t.
// ---------------------------------------------------------------------------
__global__ void bnstats_kernel(const __half* __restrict__ act,
                               const float* __restrict__ gamma,
                               const float* __restrict__ beta,
                               float* __restrict__ s_out,
                               float* __restrict__ t_out, int n, int C) {
    int c = blockIdx.x;
    double sum = 0.0, sum2 = 0.0;
    for (int e = threadIdx.x; e < n; e += blockDim.x) {
        float v = __half2float(act[e * C + c]);
        sum += v;
        sum2 += (double)v * v;
    }
    __shared__ double shs[256];
    __shared__ double sh2[256];
    shs[threadIdx.x] = sum;
    sh2[threadIdx.x] = sum2;
    __syncthreads();
    for (int o = 128; o > 0; o >>= 1) {
        if (threadIdx.x < o) {
            shs[threadIdx.x] += shs[threadIdx.x + o];
            sh2[threadIdx.x] += sh2[threadIdx.x + o];
        }
        __syncthreads();
    }
    if (threadIdx.x == 0) {
        double mean = shs[0] / n;
        double var = sh2[0] / n - mean * mean;
        double sv = (double)gamma[c] * rsqrt(var + 1e-5);
        s_out[c] = (float)sv;
        t_out[c] = (float)((double)beta[c] - mean * sv);
    }
}

// ---------------------------------------------------------------------------
// Head: BN3 affine + avgpool(2x2) + fc(128->1) + sigmoid.
// ---------------------------------------------------------------------------
__global__ void head_kernel(const __half* __restrict__ act4,
                            const float* __restrict__ s,
                            const float* __restrict__ t,
                            const float* __restrict__ fcw,
                            const float* __restrict__ fcb,
                            float* __restrict__ out) {
    int b = blockIdx.x;
    int c = threadIdx.x;
    const __half* p = act4 + b * 4 * 128;
    float mval = 0.25f * (__half2float(p[c]) + __half2float(p[128 + c]) +
                          __half2float(p[256 + c]) + __half2float(p[384 + c]));
    float v = (s[c] * mval + t[c]) * fcw[c];
    __shared__ float sh[128];
    sh[c] = v;
    __syncthreads();
    for (int o = 64; o > 0; o >>= 1) {
        if (c < o) sh[c] += sh[c + o];
        __syncthreads();
    }
    if (c == 0) {
        float zv = sh[0] + fcb[0];
        out[b] = 1.0f / (1.0f + expf(-zv));
    }
}

// ---------------------------------------------------------------------------
// Launch
// ---------------------------------------------------------------------------
extern "C" void kernel_launch(void* const* d_in, const int* in_sizes, int n_in,
                              void* d_out, int out_size) {
    const float* x   = (const float*)d_in[0];
    const float* bw1 = (const float*)d_in[1];
    const float* sw1 = (const float*)d_in[2];
    const float* sc1 = (const float*)d_in[3];
    const float* bw2 = (const float*)d_in[4];
    const float* sw2 = (const float*)d_in[5];
    const float* sc2 = (const float*)d_in[6];
    const float* bw3 = (const float*)d_in[7];
    const float* sw3 = (const float*)d_in[8];
    const float* sc3 = (const float*)d_in[9];
    const float* bw4 = (const float*)d_in[10];
    const float* sw4 = (const float*)d_in[11];
    const float* sc4 = (const float*)d_in[12];
    const float* g1  = (const float*)d_in[13];
    const float* b1  = (const float*)d_in[14];
    const float* g2  = (const float*)d_in[15];
    const float* b2  = (const float*)d_in[16];
    const float* g3  = (const float*)d_in[17];
    const float* b3  = (const float*)d_in[18];
    const float* fcw = (const float*)d_in[19];
    const float* fcb = (const float*)d_in[20];
    float* out = (float*)d_out;

    __half *whi, *wlo, *act1, *act2, *act3, *act4;
    float *part;
    float *s1, *t1, *s2, *t2, *s3, *t3;
    cudaGetSymbolAddress((void**)&whi, g_Whi);
    cudaGetSymbolAddress((void**)&wlo, g_Wlo);
    cudaGetSymbolAddress((void**)&act1, g_act1);
    cudaGetSymbolAddress((void**)&act2, g_act2);
    cudaGetSymbolAddress((void**)&act3, g_act3);
    cudaGetSymbolAddress((void**)&act4, g_act4);
    cudaGetSymbolAddress((void**)&part, g_part);
    cudaGetSymbolAddress((void**)&s1, g_bnS1);
    cudaGetSymbolAddress((void**)&t1, g_bnT1);
    cudaGetSymbolAddress((void**)&s2, g_bnS2);
    cudaGetSymbolAddress((void**)&t2, g_bnT2);
    cudaGetSymbolAddress((void**)&s3, g_bnS3);
    cudaGetSymbolAddress((void**)&t3, g_bnT3);

    const int SMEM64 = 2 * (16384 + 2 * 64 * 128) + 1024;
    const int SMEM32 = 2 * (16384 + 2 * 32 * 128) + 1024;
    cudaFuncSetAttribute(kan_mma_kernel<32, float>,
                         cudaFuncAttributeMaxDynamicSharedMemorySize, SMEM32);
    cudaFuncSetAttribute(kan_mma_kernel<64, __half>,
                         cudaFuncAttributeMaxDynamicSharedMemorySize, SMEM64);

    // ---- Layer 1: (512,3,32,32) NCHW fp32 -> act1 fp16 ----------------------
    {
        const int F = 48, O = 32, M = 512 * 16 * 16, Kpad = 8 * F;
        build_wsplit_kernel<<<(O * Kpad + 255) / 256, 256>>>(
            bw1, sw1, sc1, whi, wlo, F, O, Kpad, 0, 3);
        kan_mma_kernel<32, float><<<dim3(M / 128, 1, 1), 256, SMEM32>>>(
            x, whi, wlo, part, nullptr, nullptr, M, O, 3, 32, 4, 1, F, Kpad, 0, 0);
        reduce_splitk_kernel<<<(M * O + 255) / 256, 256>>>(part, act1, M * O, 1);
    }
    // ---- Layer 2: -> act2 fp16 via split2, BN1 stats ------------------------
    {
        const int F = 512, O = 64, M = 512 * 8 * 8, Kpad = 8 * F;
        const int SPLIT = 2;
        build_wsplit_kernel<<<(O * Kpad + 255) / 256, 256>>>(
            bw2, sw2, sc2, whi, wlo, F, O, Kpad, 1, 32);
        kan_mma_kernel<64, __half><<<dim3(M / 128, 1, SPLIT), 256, SMEM64>>>(
            act1, whi, wlo, part, nullptr, nullptr, M, O, 32, 16, 3, 0,
            F / SPLIT, Kpad, 1, 5);
        reduce_splitk_kernel<<<(M * O + 255) / 256, 256>>>(part, act2, M * O, SPLIT);
        bnstats_kernel<<<64, 256>>>(act2, g1, b1, s1, t1, 512 * 64, 64);
    }
    // ---- Layer 3: BN1 fused -> act3 fp16 via split4, BN2 stats --------------
    {
        const int F = 1024, O = 128, M = 512 * 4 * 4, Kpad = 8 * F;
        const int SPLIT = 4;
        build_wsplit_kernel<<<(O * Kpad + 255) / 256, 256>>>(
            bw3, sw3, sc3, whi, wlo, F, O, Kpad, 1, 64);
        kan_mma_kernel<64, __half><<<dim3(M / 128, O / 64, SPLIT), 256, SMEM64>>>(
            act2, whi, wlo, part, s1, t1, M, O, 64, 8, 2, 0, F / SPLIT, Kpad, 1, 6);
        reduce_splitk_kernel<<<(M * O + 255) / 256, 256>>>(part, act3, M * O, SPLIT);
        bnstats_kernel<<<128, 256>>>(act3, g2, b2, s2, t2, 512 * 16, 128);
    }
    // ---- Layer 4: BN2 fused -> act4 fp16 via split8, BN3 stats --------------
    {
        const int F = 2048, O = 128, M = 512 * 2 * 2, Kpad = 8 * F;
        const int SPLIT = 8;
        build_wsplit_kernel<<<(O * Kpad + 255) / 256, 256>>>(
            bw4, sw4, sc4, whi, wlo, F, O, Kpad, 1, 128);
        kan_mma_kernel<64, __half><<<dim3(M / 128, O / 64, SPLIT), 256, SMEM64>>>(
            act3, whi, wlo, part, s2, t2, M, O, 128, 4, 1, 0, F / SPLIT, Kpad, 1, 7);
        reduce_splitk_kernel<<<(M * O + 255) / 256, 256>>>(part, act4, M * O, SPLIT);
        bnstats_kernel<<<128, 256>>>(act4, g3, b3, s3, t3, 512 * 4, 128);
    }
    // ---- Head --------------------------------------------------------------
    head_kernel<<<512, 128>>>(act4, s3, t3, fcw, fcb, out);
}

// round 14
// speedup vs baseline: 5.0546x; 1.0378x over previous
#include <cuda_runtime.h>
#include <cuda_fp16.h>
#include <math.h>
#include <stdint.h>

// ---------------------------------------------------------------------------
// Scratch (device globals; allocation-free). ~48 MB total.
// ---------------------------------------------------------------------------
__device__ __align__(16) __half g_Whi[4194304];  // all 4 layers, packed
__device__ __align__(16) __half g_Wlo[4194304];
__device__ __align__(16) __half g_act1[4194304]; // (512,16,16,32) NHWC fp16
__device__ __align__(16) __half g_act2[2097152]; // (512,8,8,64)   NHWC fp16
__device__ __align__(16) __half g_act3[1048576]; // (512,4,4,128)  NHWC fp16
__device__ __align__(16) __half g_act4[262144];  // (512,2,2,128)  NHWC fp16
__device__ float g_part[4194304];     // split-K fp32 partials (16 MB):
                                      // L2 2x32768x64, L3 4x8192x128 = 4.19M fl
__device__ float g_bnS1[64],  g_bnT1[64];
__device__ float g_bnS2[128], g_bnT2[128];
__device__ float g_bnS3[128], g_bnT3[128];

// Packed W offsets (elements): L1 32*384, L2 64*4096, L3 128*8192, L4 128*16384
#define WOFF1 0
#define WOFF2 12288
#define WOFF3 274432
#define WOFF4 1323008

// ---------------------------------------------------------------------------
// Helpers
// ---------------------------------------------------------------------------
__device__ __forceinline__ uint32_t smem_u32(const void* p) {
    uint32_t a;
    asm("{ .reg .u64 t; cvta.to.shared.u64 t, %1; cvt.u32.u64 %0, t; }"
        : "=r"(a) : "l"(p));
    return a;
}
__device__ __forceinline__ uint32_t sw128(uint32_t off) {
    return off ^ ((off >> 3) & 0x70);
}
__device__ __forceinline__ void sts128(uint32_t addr, uint32_t a, uint32_t b,
                                       uint32_t c, uint32_t d) {
    asm volatile("st.shared.v4.b32 [%0], {%1, %2, %3, %4};"
                 :: "r"(addr), "r"(a), "r"(b), "r"(c), "r"(d) : "memory");
}
__device__ __forceinline__ void cp16(uint32_t dst, const void* src) {
    asm volatile("cp.async.cg.shared.global [%0], [%1], 16;"
                 :: "r"(dst), "l"(src) : "memory");
}
__device__ __forceinline__ void cp_commit() {
    asm volatile("cp.async.commit_group;" ::: "memory");
}
template <int N>
__device__ __forceinline__ void cp_wait() {
    asm volatile("cp.async.wait_group %0;" :: "n"(N) : "memory");
}
__device__ __forceinline__ void ldsm_x4(uint32_t* r, uint32_t addr) {
    asm volatile("ldmatrix.sync.aligned.m8n8.x4.shared.b16 {%0,%1,%2,%3}, [%4];"
                 : "=r"(r[0]), "=r"(r[1]), "=r"(r[2]), "=r"(r[3]) : "r"(addr));
}
__device__ __forceinline__ void mma16816(float* c, const uint32_t* a, const uint32_t* b) {
    asm volatile(
        "mma.sync.aligned.m16n8k16.row.col.f32.f16.f16.f32 "
        "{%0,%1,%2,%3}, {%4,%5,%6,%7}, {%8,%9}, {%0,%1,%2,%3};"
        : "+f"(c[0]), "+f"(c[1]), "+f"(c[2]), "+f"(c[3])
        : "r"(a[0]), "r"(a[1]), "r"(a[2]), "r"(a[3]), "r"(b[0]), "r"(b[1]));
}
__device__ __forceinline__ uint32_t h2pack(float a, float b) {
    __half2 h = __floats2half2_rn(a, b);
    return *reinterpret_cast<uint32_t*>(&h);
}
__device__ __forceinline__ float ldval(const float* p, int off) { return p[off]; }
__device__ __forceinline__ float ldval(const __half* p, int off) {
    return __half2float(p[off]);
}
__device__ __forceinline__ void storepair(float* dst, float a, float b) {
    *(float2*)dst = make_float2(a, b);
}
__device__ __forceinline__ void storepair(__half* dst, float a, float b) {
    *(__half2*)dst = __floats2half2_rn(a, b);
}

// ---------------------------------------------------------------------------
// Closed-form quadratic B-spline (grid_size=3, order=2, uniform knots).
// ---------------------------------------------------------------------------
__device__ __forceinline__ void spline5(float x, float* bo) {
    float u = (x + 7.0f / 3.0f) * 1.5f;
    float fi = floorf(u);
    int i = (int)fi;
    float t = u - fi;
    float omt = 1.0f - t;
    float q0 = 0.5f * omt * omt;
    float q2 = 0.5f * t * t;
    float q1 = 1.0f - q0 - q2;
#pragma unroll
    for (int j = 0; j < 5; j++) {
        float v = 0.0f;
        v = (j == i - 2) ? q0 : v;
        v = (j == i - 1) ? q1 : v;
        v = (j == i)     ? q2 : v;
        bo[j] = v;
    }
}

// ---------------------------------------------------------------------------
// Fused weight build for all 4 layers (one launch). Each segment: W[o][k],
// k = f*8 + t; corder=1 permutes f = r*Cin + c -> fsrc = c*16 + r.
// ---------------------------------------------------------------------------
struct BArgs {
    const float *bw, *sw, *sc;
    int F, O, Kpad, corder, Cin, woff, count;  // count = O*Kpad
};
__device__ __forceinline__ void build_one(const BArgs& a, int idx,
                                          __half* whi, __half* wlo) {
    int o = idx / a.Kpad;
    int k = idx - o * a.Kpad;
    int f = k >> 3;
    int t = k & 7;
    int fsrc = f;
    if (a.corder) {
        int r = f / a.Cin;
        int c = f - r * a.Cin;
        fsrc = c * 16 + r;
    }
    float val = 0.0f;
    if (t == 0)      val = a.bw[o * a.F + fsrc];
    else if (t <= 5) val = a.sw[(o * a.F + fsrc) * 5 + (t - 1)] * a.sc[o * a.F + fsrc];
    __half h = __float2half_rn(val);
    __half l = __float2half_rn(val - __half2float(h));
    whi[a.woff + idx] = h;
    wlo[a.woff + idx] = l;
}
__global__ void build_all_kernel(BArgs a0, BArgs a1, BArgs a2, BArgs a3,
                                 __half* __restrict__ whi,
                                 __half* __restrict__ wlo) {
    int idx = blockIdx.x * blockDim.x + threadIdx.x;
    if (idx < a0.count) { build_one(a0, idx, whi, wlo); return; }
    idx -= a0.count;
    if (idx < a1.count) { build_one(a1, idx, whi, wlo); return; }
    idx -= a1.count;
    if (idx < a2.count) { build_one(a2, idx, whi, wlo); return; }
    idx -= a2.count;
    if (idx < a3.count) { build_one(a3, idx, whi, wlo); }
}

// ---------------------------------------------------------------------------
// Fused KAN-conv GEMM on mma.sync (fp16 A, fp16 W hi/lo 2-term, fp32 accum).
// BM=128 x BN, 8 warps (4M x 2N). Double-buffered chunks. Window-major
// gather (corder=1) uses incremental addressing: full index math only at
// r-boundaries (every Cin/8 chunks), else poff += 8. grid.z splits K.
// OutT=float -> split-K partials; OutT=__half -> direct fp16 activation.
// ---------------------------------------------------------------------------
template <int BN, typename SrcT, typename OutT>
__global__ __launch_bounds__(256, 3)
void kan_mma_kernel(const SrcT* __restrict__ src,
                    const __half* __restrict__ Whi,
                    const __half* __restrict__ Wlo,
                    OutT* __restrict__ C,
                    const float* __restrict__ bns,
                    const float* __restrict__ bnt,
                    int M, int O, int Cin, int Hin, int hs, int nchw,
                    int fCount, int Kpad, int corder, int cinShift) {
    constexpr int BM = 128;
    constexpr int BF = 8;
    constexpr int WN = BN / 2;
    constexpr int NA = WN / 8;
    constexpr int NPAIR = NA / 2;
    constexpr int A_BYTES = BM * 128;
    constexpr int B_BYTES = BN * 128;
    constexpr int BUF_STRIDE = A_BYTES + 2 * B_BYTES;
    constexpr int BITER = (BN * 8) / 256;

    extern __shared__ char dynsmem[];
    uintptr_t tbase = ((uintptr_t)dynsmem + 1023) & ~(uintptr_t)1023;
    const uint32_t base0 = smem_u32((void*)tbase);

    const int tid = threadIdx.x;
    const int lane = tid & 31;
    const int wid = tid >> 5;
    const int warp_m = wid & 3;
    const int warp_n = wid >> 2;

    const int z = blockIdx.z;
    const int fBase = z * fCount;
    const int row0 = blockIdx.x * BM;
    const int col0 = blockIdx.y * BN;
    OutT* Cz = C + z * M * O;

    float acc[2][NA][4];
#pragma unroll
    for (int i = 0; i < 2; i++)
#pragma unroll
        for (int j = 0; j < NA; j++)
#pragma unroll
            for (int q = 0; q < 4; q++) acc[i][j][q] = 0.0f;

    const int Hout = 1 << hs;
    const int hwMask = (Hout * Hout) - 1;
    const int hwShift = 2 * hs;
    const int NC = fCount / BF;

    const uint32_t aRowOff = (uint32_t)(lane & 15) * 128 + ((uint32_t)(lane >> 4) << 4);
    const uint32_t bRowOff = ((uint32_t)((lane & 7) + ((lane >> 4) << 3))) * 128 +
                             (((uint32_t)(lane >> 3) & 1u) << 4);
    uint32_t aOffSw[2], bOffSw[NPAIR];
#pragma unroll
    for (int am = 0; am < 2; am++)
        aOffSw[am] = sw128((uint32_t)((warp_m * 32 + am * 16) * 128) + aRowOff);
#pragma unroll
    for (int pr = 0; pr < NPAIR; pr++)
        bOffSw[pr] = sw128((uint32_t)((warp_n * WN + pr * 16) * 128) + bRowOff);

    const int c_off = tid & 7;

    // Hoisted A-store swizzled offsets (chunk-invariant)
    uint32_t swA[4];
#pragma unroll
    for (int it = 0; it < 4; it++) {
        int mLocal, fl;
        if (corder) { mLocal = (tid >> 3) + it * 32; fl = c_off; }
        else        { int l = tid + it * 256; mLocal = l & (BM - 1); fl = l >> 7; }
        swA[it] = sw128((uint32_t)(mLocal * 128 + fl * 16));
    }
    // Hoisted B offsets (incremental gidx)
    uint32_t swB[BITER];
    int gidxB[BITER];
#pragma unroll
    for (int it = 0; it < BITER; it++) {
        const int l = tid + it * 256;
        const int rown = l >> 3;
        const int cg = l & 7;
        swB[it] = sw128((uint32_t)(rown * 128 + cg * 16));
        gidxB[it] = (col0 + rown) * Kpad + fBase * 8 + cg * 8;
    }

    // Incremental gather state (corder=1)
    float pv[4];
    int poff[4];
    unsigned pvmask = 0;
    int pc = 0;

    auto prefA = [&](int cc) {
        if (corder) {
            const int fc = fBase + cc * BF;
            if ((fc & (Cin - 1)) == 0) {
                const int r = fc >> cinShift;
                pc = c_off;
                const int wi = r >> 2, wj = r & 3;
                pvmask = 0;
#pragma unroll
                for (int it = 0; it < 4; it++) {
                    const int m = row0 + (tid >> 3) + it * 32;
                    const int p = m & hwMask;
                    const int b = m >> hwShift;
                    const int ho = p >> hs, wo = p & (Hout - 1);
                    const int ih = 2 * ho + wi - 1;
                    const int iw = 2 * wo + wj - 1;
                    poff[it] = (((b * Hin + ih) * Hin + iw) << cinShift) + pc;
                    if ((unsigned)ih < (unsigned)Hin && (unsigned)iw < (unsigned)Hin)
                        pvmask |= 1u << it;
                }
            } else {
                pc += BF;
#pragma unroll
                for (int it = 0; it < 4; it++) poff[it] += BF;
            }
            float s = 1.0f, t = 0.0f;
            if (bns) { s = bns[pc]; t = bnt[pc]; }
#pragma unroll
            for (int it = 0; it < 4; it++) {
                float v = 0.0f;
                if ((pvmask >> it) & 1u) {
                    v = ldval(src, poff[it]);
                    v = fmaf(v, s, t);
                }
                pv[it] = v;
            }
        } else {
#pragma unroll
            for (int it = 0; it < 4; it++) {
                const int l = tid + it * 256;
                const int mLocal = l & (BM - 1);
                const int fl = l >> 7;
                const int m = row0 + mLocal;
                const int f = fBase + cc * BF + fl;
                const int p = m & hwMask;
                const int b = m >> hwShift;
                const int ho = p >> hs, wo = p & (Hout - 1);
                const int c = f >> 4;
                const int r = f & 15;
                const int ih = 2 * ho + (r >> 2) - 1;
                const int iw = 2 * wo + (r & 3) - 1;
                float v = 0.0f;
                if ((unsigned)ih < (unsigned)Hin && (unsigned)iw < (unsigned)Hin) {
                    int off = nchw
                        ? (((b * Cin + c) * Hin + ih) * Hin + iw)
                        : (((b * Hin + ih) * Hin + iw) * Cin + c);
                    v = ldval(src, off);
                    if (bns) v = fmaf(v, bns[c], bnt[c]);
                }
                pv[it] = v;
            }
        }
    };
    auto issueB = [&](int cc) {
        const int buf = cc & 1;
        const uint32_t BH0 = base0 + buf * BUF_STRIDE + A_BYTES;
        const uint32_t BL0 = BH0 + B_BYTES;
        const int kadd = cc * BF * 8;
#pragma unroll
        for (int it = 0; it < BITER; it++) {
            cp16(BH0 + swB[it], Whi + gidxB[it] + kadd);
            cp16(BL0 + swB[it], Wlo + gidxB[it] + kadd);
        }
        cp_commit();
    };

    issueB(0);
    prefA(0);

    for (int cch = 0; cch < NC; cch++) {
        const int buf = cch & 1;
        const uint32_t A0 = base0 + buf * BUF_STRIDE;
        const uint32_t BH0 = A0 + A_BYTES;
        const uint32_t BL0 = BH0 + B_BYTES;

        // ---- expand + store A ----
#pragma unroll
        for (int it = 0; it < 4; it++) {
            const float v = pv[it];
            float vals[6];
            vals[0] = fmaxf(v, 0.0f);
            spline5(v, &vals[1]);
            sts128(A0 + swA[it], h2pack(vals[0], vals[1]), h2pack(vals[2], vals[3]),
                   h2pack(vals[4], vals[5]), 0u);
        }
        cp_wait<0>();
        __syncthreads();

        if (cch + 1 < NC) {
            issueB(cch + 1);
            prefA(cch + 1);
        }

        // ---- MMA: 4 K16 steps, 2 split terms ----
#pragma unroll
        for (int ks = 0; ks < 4; ks++) {
            const uint32_t kb = (uint32_t)(ks * 32);
            uint32_t ah[2][4];
#pragma unroll
            for (int am = 0; am < 2; am++)
                ldsm_x4(ah[am], A0 + (aOffSw[am] ^ kb));
            uint32_t bh[NA][2], bl[NA][2];
#pragma unroll
            for (int pr = 0; pr < NPAIR; pr++) {
                uint32_t t[4];
                ldsm_x4(t, BH0 + (bOffSw[pr] ^ kb));
                bh[2 * pr][0] = t[0]; bh[2 * pr][1] = t[1];
                bh[2 * pr + 1][0] = t[2]; bh[2 * pr + 1][1] = t[3];
                ldsm_x4(t, BL0 + (bOffSw[pr] ^ kb));
                bl[2 * pr][0] = t[0]; bl[2 * pr][1] = t[1];
                bl[2 * pr + 1][0] = t[2]; bl[2 * pr + 1][1] = t[3];
            }
#pragma unroll
            for (int am = 0; am < 2; am++)
#pragma unroll
                for (int an = 0; an < NA; an++) {
                    mma16816(acc[am][an], ah[am], bh[an]);
                    mma16816(acc[am][an], ah[am], bl[an]);
                }
        }
    }

    // ---- epilogue ----
#pragma unroll
    for (int am = 0; am < 2; am++) {
        const int rr = row0 + warp_m * 32 + am * 16 + (lane >> 2);
#pragma unroll
        for (int an = 0; an < NA; an++) {
            const int cc = col0 + warp_n * WN + an * 8 + (lane & 3) * 2;
            storepair(&Cz[rr * O + cc], acc[am][an][0], acc[am][an][1]);
            storepair(&Cz[(rr + 8) * O + cc], acc[am][an][2], acc[am][an][3]);
        }
    }
}

// ---------------------------------------------------------------------------
// Split-K reduce -> fp16 activation (deterministic)
// ---------------------------------------------------------------------------
__global__ void reduce_splitk_kernel(const float* __restrict__ part,
                                     __half* __restrict__ out, int MN, int S) {
    int idx = blockIdx.x * blockDim.x + threadIdx.x;
    if (idx >= MN) return;
    float a = 0.0f;
    for (int s = 0; s < S; s++) a += part[s * MN + idx];
    out[idx] = __float2half_rn(a);
}

// ---------------------------------------------------------------------------
// BN statistics on fp16 activations -> fused affine y = x*s + t.
// ---------------------------------------------------------------------------
__global__ void bnstats_kernel(const __half* __restrict__ act,
                               const float* __restrict__ gamma,
                               const float* __restrict__ beta,
                               float* __restrict__ s_out,
                               float* __restrict__ t_out, int n, int C) {
    int c = blockIdx.x;
    double sum = 0.0, sum2 = 0.0;
    for (int e = threadIdx.x; e < n; e += blockDim.x) {
        float v = __half2float(act[e * C + c]);
        sum += v;
        sum2 += (double)v * v;
    }
    __shared__ double shs[256];
    __shared__ double sh2[256];
    shs[threadIdx.x] = sum;
    sh2[threadIdx.x] = sum2;
    __syncthreads();
    for (int o = 128; o > 0; o >>= 1) {
        if (threadIdx.x < o) {
            shs[threadIdx.x] += shs[threadIdx.x + o];
            sh2[threadIdx.x] += sh2[threadIdx.x + o];
        }
        __syncthreads();
    }
    if (threadIdx.x == 0) {
        double mean = shs[0] / n;
        double var = sh2[0] / n - mean * mean;
        double sv = (double)gamma[c] * rsqrt(var + 1e-5);
        s_out[c] = (float)sv;
        t_out[c] = (float)((double)beta[c] - mean * sv);
    }
}

// ---------------------------------------------------------------------------
// Head: BN3 affine + avgpool(2x2) + fc(128->1) + sigmoid.
// ---------------------------------------------------------------------------
__global__ void head_kernel(const __half* __restrict__ act4,
                            const float* __restrict__ s,
                            const float* __restrict__ t,
                            const float* __restrict__ fcw,
                            const float* __restrict__ fcb,
                            float* __restrict__ out) {
    int b = blockIdx.x;
    int c = threadIdx.x;
    const __half* p = act4 + b * 4 * 128;
    float mval = 0.25f * (__half2float(p[c]) + __half2float(p[128 + c]) +
                          __half2float(p[256 + c]) + __half2float(p[384 + c]));
    float v = (s[c] * mval + t[c]) * fcw[c];
    __shared__ float sh[128];
    sh[c] = v;
    __syncthreads();
    for (int o = 64; o > 0; o >>= 1) {
        if (c < o) sh[c] += sh[c + o];
        __syncthreads();
    }
    if (c == 0) {
        float zv = sh[0] + fcb[0];
        out[b] = 1.0f / (1.0f + expf(-zv));
    }
}

// ---------------------------------------------------------------------------
// Launch
// ---------------------------------------------------------------------------
extern "C" void kernel_launch(void* const* d_in, const int* in_sizes, int n_in,
                              void* d_out, int out_size) {
    const float* x   = (const float*)d_in[0];
    const float* bw1 = (const float*)d_in[1];
    const float* sw1 = (const float*)d_in[2];
    const float* sc1 = (const float*)d_in[3];
    const float* bw2 = (const float*)d_in[4];
    const float* sw2 = (const float*)d_in[5];
    const float* sc2 = (const float*)d_in[6];
    const float* bw3 = (const float*)d_in[7];
    const float* sw3 = (const float*)d_in[8];
    const float* sc3 = (const float*)d_in[9];
    const float* bw4 = (const float*)d_in[10];
    const float* sw4 = (const float*)d_in[11];
    const float* sc4 = (const float*)d_in[12];
    const float* g1  = (const float*)d_in[13];
    const float* b1  = (const float*)d_in[14];
    const float* g2  = (const float*)d_in[15];
    const float* b2  = (const float*)d_in[16];
    const float* g3  = (const float*)d_in[17];
    const float* b3  = (const float*)d_in[18];
    const float* fcw = (const float*)d_in[19];
    const float* fcb = (const float*)d_in[20];
    float* out = (float*)d_out;

    __half *whi, *wlo, *act1, *act2, *act3, *act4;
    float *part;
    float *s1, *t1, *s2, *t2, *s3, *t3;
    cudaGetSymbolAddress((void**)&whi, g_Whi);
    cudaGetSymbolAddress((void**)&wlo, g_Wlo);
    cudaGetSymbolAddress((void**)&act1, g_act1);
    cudaGetSymbolAddress((void**)&act2, g_act2);
    cudaGetSymbolAddress((void**)&act3, g_act3);
    cudaGetSymbolAddress((void**)&act4, g_act4);
    cudaGetSymbolAddress((void**)&part, g_part);
    cudaGetSymbolAddress((void**)&s1, g_bnS1);
    cudaGetSymbolAddress((void**)&t1, g_bnT1);
    cudaGetSymbolAddress((void**)&s2, g_bnS2);
    cudaGetSymbolAddress((void**)&t2, g_bnT2);
    cudaGetSymbolAddress((void**)&s3, g_bnS3);
    cudaGetSymbolAddress((void**)&t3, g_bnT3);

    const int SMEM64 = 2 * (16384 + 2 * 64 * 128) + 1024;
    const int SMEM32 = 2 * (16384 + 2 * 32 * 128) + 1024;
    cudaFuncSetAttribute(kan_mma_kernel<32, float, __half>,
                         cudaFuncAttributeMaxDynamicSharedMemorySize, SMEM32);
    cudaFuncSetAttribute(kan_mma_kernel<64, __half, float>,
                         cudaFuncAttributeMaxDynamicSharedMemorySize, SMEM64);

    // ---- Fused weight build (all layers, one launch) ------------------------
    {
        BArgs a1 = {bw1, sw1, sc1, 48,   32, 384,   0, 3,   WOFF1, 32 * 384};
        BArgs a2 = {bw2, sw2, sc2, 512,  64, 4096,  1, 32,  WOFF2, 64 * 4096};
        BArgs a3 = {bw3, sw3, sc3, 1024, 128, 8192, 1, 64,  WOFF3, 128 * 8192};
        BArgs a4 = {bw4, sw4, sc4, 2048, 128, 16384, 1, 128, WOFF4, 128 * 16384};
        int total = a1.count + a2.count + a3.count + a4.count;
        build_all_kernel<<<(total + 255) / 256, 256>>>(a1, a2, a3, a4, whi, wlo);
    }
    // ---- Layer 1: (512,3,32,32) NCHW fp32 -> act1 fp16 directly -------------
    {
        const int F = 48, O = 32, M = 512 * 16 * 16, Kpad = 8 * F;
        kan_mma_kernel<32, float, __half><<<dim3(M / 128, 1, 1), 256, SMEM32>>>(
            x, whi + WOFF1, wlo + WOFF1, act1, nullptr, nullptr,
            M, O, 3, 32, 4, 1, F, Kpad, 0, 0);
    }
    // ---- Layer 2: -> act2 fp16 via split2, BN1 stats ------------------------
    {
        const int F = 512, O = 64, M = 512 * 8 * 8, Kpad = 8 * F;
        const int SPLIT = 2;
        kan_mma_kernel<64, __half, float><<<dim3(M / 128, 1, SPLIT), 256, SMEM64>>>(
            act1, whi + WOFF2, wlo + WOFF2, part, nullptr, nullptr,
            M, O, 32, 16, 3, 0, F / SPLIT, Kpad, 1, 5);
        reduce_splitk_kernel<<<(M * O + 255) / 256, 256>>>(part, act2, M * O, SPLIT);
        bnstats_kernel<<<64, 256>>>(act2, g1, b1, s1, t1, 512 * 64, 64);
    }
    // ---- Layer 3: BN1 fused -> act3 fp16 via split4, BN2 stats --------------
    {
        const int F = 1024, O = 128, M = 512 * 4 * 4, Kpad = 8 * F;
        const int SPLIT = 4;
        kan_mma_kernel<64, __half, float><<<dim3(M / 128, O / 64, SPLIT), 256, SMEM64>>>(
            act2, whi + WOFF3, wlo + WOFF3, part, s1, t1,
            M, O, 64, 8, 2, 0, F / SPLIT, Kpad, 1, 6);
        reduce_splitk_kernel<<<(M * O + 255) / 256, 256>>>(part, act3, M * O, SPLIT);
        bnstats_kernel<<<128, 256>>>(act3, g2, b2, s2, t2, 512 * 16, 128);
    }
    // ---- Layer 4: BN2 fused -> act4 fp16 via split8, BN3 stats --------------
    {
        const int F = 2048, O = 128, M = 512 * 2 * 2, Kpad = 8 * F;
        const int SPLIT = 8;
        kan_mma_kernel<64, __half, float><<<dim3(M / 128, O / 64, SPLIT), 256, SMEM64>>>(
            act3, whi + WOFF4, wlo + WOFF4, part, s2, t2,
            M, O, 128, 4, 1, 0, F / SPLIT, Kpad, 1, 7);
        reduce_splitk_kernel<<<(M * O + 255) / 256, 256>>>(part, act4, M * O, SPLIT);
        bnstats_kernel<<<128, 256>>>(act4, g3, b3, s3, t3, 512 * 4, 128);
    }
    // ---- Head --------------------------------------------------------------
    head_kernel<<<512, 128>>>(act4, s3, t3, fcw, fcb, out);
}

// round 16
// speedup vs baseline: 7.1339x; 1.4114x over previous
#include <cuda_runtime.h>
#include <cuda_fp16.h>
#include <math.h>
#include <stdint.h>

// ---------------------------------------------------------------------------
// Scratch (device globals; allocation-free). ~40 MB total.
// ---------------------------------------------------------------------------
__device__ __align__(16) __half g_W[4194304];    // all 4 layers, packed (fp16)
__device__ __align__(16) __half g_act1[4194304]; // (512,16,16,32) NHWC fp16
__device__ __align__(16) __half g_act2[2097152]; // (512,8,8,64)   NHWC fp16
__device__ __align__(16) __half g_act3[1048576]; // (512,4,4,128)  NHWC fp16
__device__ __align__(16) __half g_act4[262144];  // (512,2,2,128)  NHWC fp16
__device__ float g_part[4194304];     // split-K fp32 partials (16 MB):
                                      // L2 2x32768x64 = L3 4x8192x128 = 4.19M fl
__device__ float g_bnS1[64],  g_bnT1[64];
__device__ float g_bnS2[128], g_bnT2[128];
__device__ float g_bnS3[128], g_bnT3[128];

// Packed W offsets (elements): L1 32*384, L2 64*4096, L3 128*8192, L4 128*16384
#define WOFF1 0
#define WOFF2 12288
#define WOFF3 274432
#define WOFF4 1323008

// ---------------------------------------------------------------------------
// Helpers
// ---------------------------------------------------------------------------
__device__ __forceinline__ uint32_t smem_u32(const void* p) {
    uint32_t a;
    asm("{ .reg .u64 t; cvta.to.shared.u64 t, %1; cvt.u32.u64 %0, t; }"
        : "=r"(a) : "l"(p));
    return a;
}
__device__ __forceinline__ uint32_t sw128(uint32_t off) {
    return off ^ ((off >> 3) & 0x70);
}
__device__ __forceinline__ void sts128(uint32_t addr, uint32_t a, uint32_t b,
                                       uint32_t c, uint32_t d) {
    asm volatile("st.shared.v4.b32 [%0], {%1, %2, %3, %4};"
                 :: "r"(addr), "r"(a), "r"(b), "r"(c), "r"(d) : "memory");
}
__device__ __forceinline__ void cp16(uint32_t dst, const void* src) {
    asm volatile("cp.async.cg.shared.global [%0], [%1], 16;"
                 :: "r"(dst), "l"(src) : "memory");
}
__device__ __forceinline__ void cp_commit() {
    asm volatile("cp.async.commit_group;" ::: "memory");
}
template <int N>
__device__ __forceinline__ void cp_wait() {
    asm volatile("cp.async.wait_group %0;" :: "n"(N) : "memory");
}
__device__ __forceinline__ void ldsm_x4(uint32_t* r, uint32_t addr) {
    asm volatile("ldmatrix.sync.aligned.m8n8.x4.shared.b16 {%0,%1,%2,%3}, [%4];"
                 : "=r"(r[0]), "=r"(r[1]), "=r"(r[2]), "=r"(r[3]) : "r"(addr));
}
__device__ __forceinline__ void mma16816(float* c, const uint32_t* a, const uint32_t* b) {
    asm volatile(
        "mma.sync.aligned.m16n8k16.row.col.f32.f16.f16.f32 "
        "{%0,%1,%2,%3}, {%4,%5,%6,%7}, {%8,%9}, {%0,%1,%2,%3};"
        : "+f"(c[0]), "+f"(c[1]), "+f"(c[2]), "+f"(c[3])
        : "r"(a[0]), "r"(a[1]), "r"(a[2]), "r"(a[3]), "r"(b[0]), "r"(b[1]));
}
__device__ __forceinline__ uint32_t h2pack(float a, float b) {
    __half2 h = __floats2half2_rn(a, b);
    return *reinterpret_cast<uint32_t*>(&h);
}
__device__ __forceinline__ float ldval(const float* p, int off) { return p[off]; }
__device__ __forceinline__ float ldval(const __half* p, int off) {
    return __half2float(p[off]);
}
__device__ __forceinline__ void storepair(float* dst, float a, float b) {
    *(float2*)dst = make_float2(a, b);
}
__device__ __forceinline__ void storepair(__half* dst, float a, float b) {
    *(__half2*)dst = __floats2half2_rn(a, b);
}

// ---------------------------------------------------------------------------
// Closed-form quadratic B-spline (grid_size=3, order=2, uniform knots).
// ---------------------------------------------------------------------------
__device__ __forceinline__ void spline5(float x, float* bo) {
    float u = (x + 7.0f / 3.0f) * 1.5f;
    float fi = floorf(u);
    int i = (int)fi;
    float t = u - fi;
    float omt = 1.0f - t;
    float q0 = 0.5f * omt * omt;
    float q2 = 0.5f * t * t;
    float q1 = 1.0f - q0 - q2;
#pragma unroll
    for (int j = 0; j < 5; j++) {
        float v = 0.0f;
        v = (j == i - 2) ? q0 : v;
        v = (j == i - 1) ? q1 : v;
        v = (j == i)     ? q2 : v;
        bo[j] = v;
    }
}

// ---------------------------------------------------------------------------
// Fused weight build for all 4 layers (one launch). Each segment: W[o][k],
// k = f*8 + t; corder=1 permutes f = r*Cin + c -> fsrc = c*16 + r.
// ---------------------------------------------------------------------------
struct BArgs {
    const float *bw, *sw, *sc;
    int F, O, Kpad, corder, Cin, woff, count;  // count = O*Kpad
};
__device__ __forceinline__ void build_one(const BArgs& a, int idx, __half* w) {
    int o = idx / a.Kpad;
    int k = idx - o * a.Kpad;
    int f = k >> 3;
    int t = k & 7;
    int fsrc = f;
    if (a.corder) {
        int r = f / a.Cin;
        int c = f - r * a.Cin;
        fsrc = c * 16 + r;
    }
    float val = 0.0f;
    if (t == 0)      val = a.bw[o * a.F + fsrc];
    else if (t <= 5) val = a.sw[(o * a.F + fsrc) * 5 + (t - 1)] * a.sc[o * a.F + fsrc];
    w[a.woff + idx] = __float2half_rn(val);
}
__global__ void build_all_kernel(BArgs a0, BArgs a1, BArgs a2, BArgs a3,
                                 __half* __restrict__ w) {
    int idx = blockIdx.x * blockDim.x + threadIdx.x;
    if (idx < a0.count) { build_one(a0, idx, w); return; }
    idx -= a0.count;
    if (idx < a1.count) { build_one(a1, idx, w); return; }
    idx -= a1.count;
    if (idx < a2.count) { build_one(a2, idx, w); return; }
    idx -= a2.count;
    if (idx < a3.count) { build_one(a3, idx, w); }
}

// ---------------------------------------------------------------------------
// Fused KAN-conv GEMM on mma.sync (fp16 A, fp16 W single-term, fp32 accum).
// BM=128 x BN, 8 warps (4M x 2N). Double-buffered chunks. Window-major
// gather (corder=1) uses incremental addressing. grid.z splits K.
// OutT=float -> split-K partials; OutT=__half -> direct fp16 activation.
// ---------------------------------------------------------------------------
template <int BN, typename SrcT, typename OutT>
__global__ __launch_bounds__(256, (BN >= 128 ? 2 : 3))
void kan_mma_kernel(const SrcT* __restrict__ src,
                    const __half* __restrict__ W,
                    OutT* __restrict__ C,
                    const float* __restrict__ bns,
                    const float* __restrict__ bnt,
                    int M, int O, int Cin, int Hin, int hs, int nchw,
                    int fCount, int Kpad, int corder, int cinShift) {
    constexpr int BM = 128;
    constexpr int BF = 8;
    constexpr int WN = BN / 2;
    constexpr int NA = WN / 8;
    constexpr int NPAIR = NA / 2;
    constexpr int A_BYTES = BM * 128;
    constexpr int B_BYTES = BN * 128;
    constexpr int BUF_STRIDE = A_BYTES + B_BYTES;
    constexpr int BITER = (BN * 8) / 256;

    extern __shared__ char dynsmem[];
    uintptr_t tbase = ((uintptr_t)dynsmem + 1023) & ~(uintptr_t)1023;
    const uint32_t base0 = smem_u32((void*)tbase);

    const int tid = threadIdx.x;
    const int lane = tid & 31;
    const int wid = tid >> 5;
    const int warp_m = wid & 3;
    const int warp_n = wid >> 2;

    const int z = blockIdx.z;
    const int fBase = z * fCount;
    const int row0 = blockIdx.x * BM;
    const int col0 = blockIdx.y * BN;
    OutT* Cz = C + z * M * O;

    float acc[2][NA][4];
#pragma unroll
    for (int i = 0; i < 2; i++)
#pragma unroll
        for (int j = 0; j < NA; j++)
#pragma unroll
            for (int q = 0; q < 4; q++) acc[i][j][q] = 0.0f;

    const int Hout = 1 << hs;
    const int hwMask = (Hout * Hout) - 1;
    const int hwShift = 2 * hs;
    const int NC = fCount / BF;

    const uint32_t aRowOff = (uint32_t)(lane & 15) * 128 + ((uint32_t)(lane >> 4) << 4);
    const uint32_t bRowOff = ((uint32_t)((lane & 7) + ((lane >> 4) << 3))) * 128 +
                             (((uint32_t)(lane >> 3) & 1u) << 4);
    uint32_t aOffSw[2], bOffSw[NPAIR];
#pragma unroll
    for (int am = 0; am < 2; am++)
        aOffSw[am] = sw128((uint32_t)((warp_m * 32 + am * 16) * 128) + aRowOff);
#pragma unroll
    for (int pr = 0; pr < NPAIR; pr++)
        bOffSw[pr] = sw128((uint32_t)((warp_n * WN + pr * 16) * 128) + bRowOff);

    const int c_off = tid & 7;

    // Hoisted A-store swizzled offsets (chunk-invariant)
    uint32_t swA[4];
#pragma unroll
    for (int it = 0; it < 4; it++) {
        int mLocal, fl;
        if (corder) { mLocal = (tid >> 3) + it * 32; fl = c_off; }
        else        { int l = tid + it * 256; mLocal = l & (BM - 1); fl = l >> 7; }
        swA[it] = sw128((uint32_t)(mLocal * 128 + fl * 16));
    }
    // Hoisted B offsets (incremental gidx)
    uint32_t swB[BITER];
    int gidxB[BITER];
#pragma unroll
    for (int it = 0; it < BITER; it++) {
        const int l = tid + it * 256;
        const int rown = l >> 3;
        const int cg = l & 7;
        swB[it] = sw128((uint32_t)(rown * 128 + cg * 16));
        gidxB[it] = (col0 + rown) * Kpad + fBase * 8 + cg * 8;
    }

    // Incremental gather state (corder=1)
    float pv[4];
    int poff[4];
    unsigned pvmask = 0;
    int pc = 0;

    auto prefA = [&](int cc) {
        if (corder) {
            const int fc = fBase + cc * BF;
            if ((fc & (Cin - 1)) == 0) {
                const int r = fc >> cinShift;
                pc = c_off;
                const int wi = r >> 2, wj = r & 3;
                pvmask = 0;
#pragma unroll
                for (int it = 0; it < 4; it++) {
                    const int m = row0 + (tid >> 3) + it * 32;
                    const int p = m & hwMask;
                    const int b = m >> hwShift;
                    const int ho = p >> hs, wo = p & (Hout - 1);
                    const int ih = 2 * ho + wi - 1;
                    const int iw = 2 * wo + wj - 1;
                    poff[it] = (((b * Hin + ih) * Hin + iw) << cinShift) + pc;
                    if ((unsigned)ih < (unsigned)Hin && (unsigned)iw < (unsigned)Hin)
                        pvmask |= 1u << it;
                }
            } else {
                pc += BF;
#pragma unroll
                for (int it = 0; it < 4; it++) poff[it] += BF;
            }
            float s = 1.0f, t = 0.0f;
            if (bns) { s = bns[pc]; t = bnt[pc]; }
#pragma unroll
            for (int it = 0; it < 4; it++) {
                float v = 0.0f;
                if ((pvmask >> it) & 1u) {
                    v = ldval(src, poff[it]);
                    v = fmaf(v, s, t);
                }
                pv[it] = v;
            }
        } else {
#pragma unroll
            for (int it = 0; it < 4; it++) {
                const int l = tid + it * 256;
                const int mLocal = l & (BM - 1);
                const int fl = l >> 7;
                const int m = row0 + mLocal;
                const int f = fBase + cc * BF + fl;
                const int p = m & hwMask;
                const int b = m >> hwShift;
                const int ho = p >> hs, wo = p & (Hout - 1);
                const int c = f >> 4;
                const int r = f & 15;
                const int ih = 2 * ho + (r >> 2) - 1;
                const int iw = 2 * wo + (r & 3) - 1;
                float v = 0.0f;
                if ((unsigned)ih < (unsigned)Hin && (unsigned)iw < (unsigned)Hin) {
                    int off = nchw
                        ? (((b * Cin + c) * Hin + ih) * Hin + iw)
                        : (((b * Hin + ih) * Hin + iw) * Cin + c);
                    v = ldval(src, off);
                    if (bns) v = fmaf(v, bns[c], bnt[c]);
                }
                pv[it] = v;
            }
        }
    };
    auto issueB = [&](int cc) {
        const int buf = cc & 1;
        const uint32_t BH0 = base0 + buf * BUF_STRIDE + A_BYTES;
        const int kadd = cc * BF * 8;
#pragma unroll
        for (int it = 0; it < BITER; it++)
            cp16(BH0 + swB[it], W + gidxB[it] + kadd);
        cp_commit();
    };

    issueB(0);
    prefA(0);

    for (int cch = 0; cch < NC; cch++) {
        const int buf = cch & 1;
        const uint32_t A0 = base0 + buf * BUF_STRIDE;
        const uint32_t BH0 = A0 + A_BYTES;

        // ---- expand + store A ----
#pragma unroll
        for (int it = 0; it < 4; it++) {
            const float v = pv[it];
            float vals[6];
            vals[0] = fmaxf(v, 0.0f);
            spline5(v, &vals[1]);
            sts128(A0 + swA[it], h2pack(vals[0], vals[1]), h2pack(vals[2], vals[3]),
                   h2pack(vals[4], vals[5]), 0u);
        }
        cp_wait<0>();
        __syncthreads();

        if (cch + 1 < NC) {
            issueB(cch + 1);
            prefA(cch + 1);
        }

        // ---- MMA: 4 K16 steps, single weight term ----
#pragma unroll
        for (int ks = 0; ks < 4; ks++) {
            const uint32_t kb = (uint32_t)(ks * 32);
            uint32_t ah[2][4];
#pragma unroll
            for (int am = 0; am < 2; am++)
                ldsm_x4(ah[am], A0 + (aOffSw[am] ^ kb));
            uint32_t bh[NA][2];
#pragma unroll
            for (int pr = 0; pr < NPAIR; pr++) {
                uint32_t t[4];
                ldsm_x4(t, BH0 + (bOffSw[pr] ^ kb));
                bh[2 * pr][0] = t[0]; bh[2 * pr][1] = t[1];
                bh[2 * pr + 1][0] = t[2]; bh[2 * pr + 1][1] = t[3];
            }
#pragma unroll
            for (int am = 0; am < 2; am++)
#pragma unroll
                for (int an = 0; an < NA; an++)
                    mma16816(acc[am][an], ah[am], bh[an]);
        }
    }

    // ---- epilogue ----
#pragma unroll
    for (int am = 0; am < 2; am++) {
        const int rr = row0 + warp_m * 32 + am * 16 + (lane >> 2);
#pragma unroll
        for (int an = 0; an < NA; an++) {
            const int cc = col0 + warp_n * WN + an * 8 + (lane & 3) * 2;
            storepair(&Cz[rr * O + cc], acc[am][an][0], acc[am][an][1]);
            storepair(&Cz[(rr + 8) * O + cc], acc[am][an][2], acc[am][an][3]);
        }
    }
}

// ---------------------------------------------------------------------------
// Split-K reduce -> fp16 activation (deterministic)
// ---------------------------------------------------------------------------
__global__ void reduce_splitk_kernel(const float* __restrict__ part,
                                     __half* __restrict__ out, int MN, int S) {
    int idx = blockIdx.x * blockDim.x + threadIdx.x;
    if (idx >= MN) return;
    float a = 0.0f;
    for (int s = 0; s < S; s++) a += part[s * MN + idx];
    out[idx] = __float2half_rn(a);
}

// ---------------------------------------------------------------------------
// BN statistics on fp16 activations -> fused affine y = x*s + t.
// ---------------------------------------------------------------------------
__global__ void bnstats_kernel(const __half* __restrict__ act,
                               const float* __restrict__ gamma,
                               const float* __restrict__ beta,
                               float* __restrict__ s_out,
                               float* __restrict__ t_out, int n, int C) {
    int c = blockIdx.x;
    double sum = 0.0, sum2 = 0.0;
    for (int e = threadIdx.x; e < n; e += blockDim.x) {
        float v = __half2float(act[e * C + c]);
        sum += v;
        sum2 += (double)v * v;
    }
    __shared__ double shs[256];
    __shared__ double sh2[256];
    shs[threadIdx.x] = sum;
    sh2[threadIdx.x] = sum2;
    __syncthreads();
    for (int o = 128; o > 0; o >>= 1) {
        if (threadIdx.x < o) {
            shs[threadIdx.x] += shs[threadIdx.x + o];
            sh2[threadIdx.x] += sh2[threadIdx.x + o];
        }
        __syncthreads();
    }
    if (threadIdx.x == 0) {
        double mean = shs[0] / n;
        double var = sh2[0] / n - mean * mean;
        double sv = (double)gamma[c] * rsqrt(var + 1e-5);
        s_out[c] = (float)sv;
        t_out[c] = (float)((double)beta[c] - mean * sv);
    }
}

// ---------------------------------------------------------------------------
// Head: BN3 affine + avgpool(2x2) + fc(128->1) + sigmoid.
// ---------------------------------------------------------------------------
__global__ void head_kernel(const __half* __restrict__ act4,
                            const float* __restrict__ s,
                            const float* __restrict__ t,
                            const float* __restrict__ fcw,
                            const float* __restrict__ fcb,
                            float* __restrict__ out) {
    int b = blockIdx.x;
    int c = threadIdx.x;
    const __half* p = act4 + b * 4 * 128;
    float mval = 0.25f * (__half2float(p[c]) + __half2float(p[128 + c]) +
                          __half2float(p[256 + c]) + __half2float(p[384 + c]));
    float v = (s[c] * mval + t[c]) * fcw[c];
    __shared__ float sh[128];
    sh[c] = v;
    __syncthreads();
    for (int o = 64; o > 0; o >>= 1) {
        if (c < o) sh[c] += sh[c + o];
        __syncthreads();
    }
    if (c == 0) {
        float zv = sh[0] + fcb[0];
        out[b] = 1.0f / (1.0f + expf(-zv));
    }
}

// ---------------------------------------------------------------------------
// Launch
// ---------------------------------------------------------------------------
extern "C" void kernel_launch(void* const* d_in, const int* in_sizes, int n_in,
                              void* d_out, int out_size) {
    const float* x   = (const float*)d_in[0];
    const float* bw1 = (const float*)d_in[1];
    const float* sw1 = (const float*)d_in[2];
    const float* sc1 = (const float*)d_in[3];
    const float* bw2 = (const float*)d_in[4];
    const float* sw2 = (const float*)d_in[5];
    const float* sc2 = (const float*)d_in[6];
    const float* bw3 = (const float*)d_in[7];
    const float* sw3 = (const float*)d_in[8];
    const float* sc3 = (const float*)d_in[9];
    const float* bw4 = (const float*)d_in[10];
    const float* sw4 = (const float*)d_in[11];
    const float* sc4 = (const float*)d_in[12];
    const float* g1  = (const float*)d_in[13];
    const float* b1  = (const float*)d_in[14];
    const float* g2  = (const float*)d_in[15];
    const float* b2  = (const float*)d_in[16];
    const float* g3  = (const float*)d_in[17];
    const float* b3  = (const float*)d_in[18];
    const float* fcw = (const float*)d_in[19];
    const float* fcb = (const float*)d_in[20];
    float* out = (float*)d_out;

    __half *w, *act1, *act2, *act3, *act4;
    float *part;
    float *s1, *t1, *s2, *t2, *s3, *t3;
    cudaGetSymbolAddress((void**)&w, g_W);
    cudaGetSymbolAddress((void**)&act1, g_act1);
    cudaGetSymbolAddress((void**)&act2, g_act2);
    cudaGetSymbolAddress((void**)&act3, g_act3);
    cudaGetSymbolAddress((void**)&act4, g_act4);
    cudaGetSymbolAddress((void**)&part, g_part);
    cudaGetSymbolAddress((void**)&s1, g_bnS1);
    cudaGetSymbolAddress((void**)&t1, g_bnT1);
    cudaGetSymbolAddress((void**)&s2, g_bnS2);
    cudaGetSymbolAddress((void**)&t2, g_bnT2);
    cudaGetSymbolAddress((void**)&s3, g_bnS3);
    cudaGetSymbolAddress((void**)&t3, g_bnT3);

    const int SMEM32  = 2 * (16384 + 32 * 128) + 1024;   // 41984
    const int SMEM64  = 2 * (16384 + 64 * 128) + 1024;   // 50176
    const int SMEM128 = 2 * (16384 + 128 * 128) + 1024;  // 66560
    cudaFuncSetAttribute(kan_mma_kernel<32, float, __half>,
                         cudaFuncAttributeMaxDynamicSharedMemorySize, SMEM32);
    cudaFuncSetAttribute(kan_mma_kernel<64, __half, float>,
                         cudaFuncAttributeMaxDynamicSharedMemorySize, SMEM64);
    cudaFuncSetAttribute(kan_mma_kernel<128, __half, float>,
                         cudaFuncAttributeMaxDynamicSharedMemorySize, SMEM128);

    // ---- Fused weight build (all layers, one launch) ------------------------
    {
        BArgs a1 = {bw1, sw1, sc1, 48,   32, 384,   0, 3,   WOFF1, 32 * 384};
        BArgs a2 = {bw2, sw2, sc2, 512,  64, 4096,  1, 32,  WOFF2, 64 * 4096};
        BArgs a3 = {bw3, sw3, sc3, 1024, 128, 8192, 1, 64,  WOFF3, 128 * 8192};
        BArgs a4 = {bw4, sw4, sc4, 2048, 128, 16384, 1, 128, WOFF4, 128 * 16384};
        int total = a1.count + a2.count + a3.count + a4.count;
        build_all_kernel<<<(total + 255) / 256, 256>>>(a1, a2, a3, a4, w);
    }
    // ---- Layer 1: (512,3,32,32) NCHW fp32 -> act1 fp16 directly -------------
    {
        const int F = 48, O = 32, M = 512 * 16 * 16, Kpad = 8 * F;
        kan_mma_kernel<32, float, __half><<<dim3(M / 128, 1, 1), 256, SMEM32>>>(
            x, w + WOFF1, act1, nullptr, nullptr,
            M, O, 3, 32, 4, 1, F, Kpad, 0, 0);
    }
    // ---- Layer 2: -> act2 fp16 via split2, BN1 stats ------------------------
    {
        const int F = 512, O = 64, M = 512 * 8 * 8, Kpad = 8 * F;
        const int SPLIT = 2;
        kan_mma_kernel<64, __half, float><<<dim3(M / 128, 1, SPLIT), 256, SMEM64>>>(
            act1, w + WOFF2, part, nullptr, nullptr,
            M, O, 32, 16, 3, 0, F / SPLIT, Kpad, 1, 5);
        reduce_splitk_kernel<<<(M * O + 255) / 256, 256>>>(part, act2, M * O, SPLIT);
        bnstats_kernel<<<64, 256>>>(act2, g1, b1, s1, t1, 512 * 64, 64);
    }
    // ---- Layer 3: BN1 fused -> act3 fp16, BN=128 tile, split4, BN2 stats ----
    {
        const int F = 1024, O = 128, M = 512 * 4 * 4, Kpad = 8 * F;
        const int SPLIT = 4;
        kan_mma_kernel<128, __half, float><<<dim3(M / 128, 1, SPLIT), 256, SMEM128>>>(
            act2, w + WOFF3, part, s1, t1,
            M, O, 64, 8, 2, 0, F / SPLIT, Kpad, 1, 6);
        reduce_splitk_kernel<<<(M * O + 255) / 256, 256>>>(part, act3, M * O, SPLIT);
        bnstats_kernel<<<128, 256>>>(act3, g2, b2, s2, t2, 512 * 16, 128);
    }
    // ---- Layer 4: BN2 fused -> act4 fp16, BN=128 tile, split8, BN3 stats ----
    {
        const int F = 2048, O = 128, M = 512 * 2 * 2, Kpad = 8 * F;
        const int SPLIT = 8;
        kan_mma_kernel<128, __half, float><<<dim3(M / 128, 1, SPLIT), 256, SMEM128>>>(
            act3, w + WOFF4, part, s2, t2,
            M, O, 128, 4, 1, 0, F / SPLIT, Kpad, 1, 7);
        reduce_splitk_kernel<<<(M * O + 255) / 256, 256>>>(part, act4, M * O, SPLIT);
        bnstats_kernel<<<128, 256>>>(act4, g3, b3, s3, t3, 512 * 4, 128);
    }
    // ---- Head --------------------------------------------------------------
    head_kernel<<<512, 128>>>(act4, s3, t3, fcw, fcb, out);
}